// round 6
// baseline (speedup 1.0000x reference)
#include <cuda_runtime.h>
#include <cuda_bf16.h>
#include <math.h>
#include <stdint.h>

#define MHA_B  2
#define MHA_S  2048
#define MHA_D  1024
#define MHA_H  16
#define MHA_HD 64
#define NTOK   (MHA_B * MHA_S)

// ---------------------------------------------------------------------------
// Scratch (__device__ globals; allocation-free rule)
// ---------------------------------------------------------------------------
__device__ __nv_bfloat16 g_xhi[NTOK * MHA_D];
__device__ __nv_bfloat16 g_xlo[NTOK * MHA_D];

__device__ __nv_bfloat16 g_qhi[NTOK * MHA_D];
__device__ __nv_bfloat16 g_qlo[NTOK * MHA_D];
__device__ __nv_bfloat16 g_khi[NTOK * MHA_D];
__device__ __nv_bfloat16 g_klo[NTOK * MHA_D];
__device__ __nv_bfloat16 g_vhi[NTOK * MHA_D];
__device__ __nv_bfloat16 g_vlo[NTOK * MHA_D];
__device__ __nv_bfloat16 g_chi[NTOK * MHA_D];
__device__ __nv_bfloat16 g_clo[NTOK * MHA_D];

__device__ __nv_bfloat16 g_wqt_hi[MHA_D * MHA_D];
__device__ __nv_bfloat16 g_wqt_lo[MHA_D * MHA_D];
__device__ __nv_bfloat16 g_wkt_hi[MHA_D * MHA_D];
__device__ __nv_bfloat16 g_wkt_lo[MHA_D * MHA_D];
__device__ __nv_bfloat16 g_wvt_hi[MHA_D * MHA_D];
__device__ __nv_bfloat16 g_wvt_lo[MHA_D * MHA_D];
__device__ __nv_bfloat16 g_wot_hi[MHA_D * MHA_D];
__device__ __nv_bfloat16 g_wot_lo[MHA_D * MHA_D];

// ---------------------------------------------------------------------------
// Portable (sm_80+) tensor-core + async-copy helpers
// ---------------------------------------------------------------------------
__device__ __forceinline__ uint32_t smem_u32(const void* p) {
    uint32_t a;
    asm("{ .reg .u64 t; cvta.to.shared.u64 t, %1; cvt.u32.u64 %0, t; }"
        : "=r"(a) : "l"(p));
    return a;
}

__device__ __forceinline__ void ldmx4(uint32_t* r, uint32_t addr) {
    asm volatile(
        "ldmatrix.sync.aligned.m8n8.x4.shared.b16 {%0,%1,%2,%3}, [%4];"
        : "=r"(r[0]), "=r"(r[1]), "=r"(r[2]), "=r"(r[3]) : "r"(addr));
}

__device__ __forceinline__ void ldmx4t(uint32_t* r, uint32_t addr) {
    asm volatile(
        "ldmatrix.sync.aligned.m8n8.x4.trans.shared.b16 {%0,%1,%2,%3}, [%4];"
        : "=r"(r[0]), "=r"(r[1]), "=r"(r[2]), "=r"(r[3]) : "r"(addr));
}

__device__ __forceinline__ void mma16816(float* d, const uint32_t* a,
                                         uint32_t b0, uint32_t b1) {
    asm volatile(
        "mma.sync.aligned.m16n8k16.row.col.f32.bf16.bf16.f32 "
        "{%0,%1,%2,%3}, {%4,%5,%6,%7}, {%8,%9}, {%0,%1,%2,%3};"
        : "+f"(d[0]), "+f"(d[1]), "+f"(d[2]), "+f"(d[3])
        : "r"(a[0]), "r"(a[1]), "r"(a[2]), "r"(a[3]), "r"(b0), "r"(b1));
}

__device__ __forceinline__ void cpasync16(uint32_t saddr, const void* gaddr) {
    asm volatile("cp.async.cg.shared.global [%0], [%1], 16;"
                 :: "r"(saddr), "l"(gaddr));
}
#define CP_COMMIT() asm volatile("cp.async.commit_group;" ::: "memory")
#define CP_WAIT0()  asm volatile("cp.async.wait_group 0;" ::: "memory")
#define CP_WAIT1()  asm volatile("cp.async.wait_group 1;" ::: "memory")

#define SWZ128(off) ((off) ^ (((off) >> 3) & 0x70))

// ---------------------------------------------------------------------------
// Conversion kernels
// ---------------------------------------------------------------------------
__global__ void split_kernel(const float* __restrict__ in,
                             __nv_bfloat16* __restrict__ hi,
                             __nv_bfloat16* __restrict__ lo)
{
    int i = (blockIdx.x * 256 + threadIdx.x) * 4;
    float4 v = *(const float4*)(in + i);
    __nv_bfloat16 h0 = __float2bfloat16(v.x);
    __nv_bfloat16 h1 = __float2bfloat16(v.y);
    __nv_bfloat16 h2 = __float2bfloat16(v.z);
    __nv_bfloat16 h3 = __float2bfloat16(v.w);
    __nv_bfloat16 l0 = __float2bfloat16(v.x - __bfloat162float(h0));
    __nv_bfloat16 l1 = __float2bfloat16(v.y - __bfloat162float(h1));
    __nv_bfloat16 l2 = __float2bfloat16(v.z - __bfloat162float(h2));
    __nv_bfloat16 l3 = __float2bfloat16(v.w - __bfloat162float(h3));
    ((__nv_bfloat162*)hi)[i / 2]     = __nv_bfloat162(h0, h1);
    ((__nv_bfloat162*)hi)[i / 2 + 1] = __nv_bfloat162(h2, h3);
    ((__nv_bfloat162*)lo)[i / 2]     = __nv_bfloat162(l0, l1);
    ((__nv_bfloat162*)lo)[i / 2 + 1] = __nv_bfloat162(l2, l3);
}

__global__ void transpose_split_kernel(const float* __restrict__ W,
                                       __nv_bfloat16* __restrict__ Thi,
                                       __nv_bfloat16* __restrict__ Tlo)
{
    __shared__ float t[32][33];
    const int tx = threadIdx.x, ty = threadIdx.y;
    const int k0 = blockIdx.y * 32;
    const int n0 = blockIdx.x * 32;
    #pragma unroll
    for (int j = 0; j < 4; j++)
        t[ty + j * 8][tx] = W[(size_t)(k0 + ty + j * 8) * MHA_D + n0 + tx];
    __syncthreads();
    #pragma unroll
    for (int j = 0; j < 4; j++) {
        float v = t[tx][ty + j * 8];
        __nv_bfloat16 h = __float2bfloat16(v);
        __nv_bfloat16 l = __float2bfloat16(v - __bfloat162float(h));
        size_t o = (size_t)(n0 + ty + j * 8) * MHA_D + k0 + tx;
        Thi[o] = h;
        Tlo[o] = l;
    }
}

// ---------------------------------------------------------------------------
// HMMA bf16-split GEMM, cp.async double-buffered.
// C = A * B (+bias), optional split-bf16 output.
// A as (Ahi, Alo) row-major [M][K]; B as (Bhi, Blo) = B^T [N][K].
// CTA: 128x128 tile, BK=64, 8 warps 4(m)x2(n), warp tile 32x64.
// ---------------------------------------------------------------------------
#define GM_M 4096
#define GM_N 1024
#define GM_K 1024
#define GT_M 128
#define GT_N 128
#define GT_K 64
#define GM_NK (GM_K / GT_K)     // 16

#define TILE_B (GT_M * GT_K * 2)     // 16 KB
#define SM_AHI 0
#define SM_ALO TILE_B
#define SM_BHI (2 * TILE_B)
#define SM_BLO (3 * TILE_B)
#define STG_B  (4 * TILE_B)          // 64 KB per stage
#define SM_GEMM_TOTAL (2 * STG_B)    // 128 KB

template <bool SPLIT, bool BIAS>
__global__ __launch_bounds__(256, 1) void gemm_hmma_kernel(
    const __nv_bfloat16* __restrict__ Ahi, const __nv_bfloat16* __restrict__ Alo,
    const __nv_bfloat16* __restrict__ Bhi, const __nv_bfloat16* __restrict__ Blo,
    const float* __restrict__ bias, float* __restrict__ C,
    __nv_bfloat16* __restrict__ Ohi, __nv_bfloat16* __restrict__ Olo,
    float scale)
{
    extern __shared__ char smem[];
    const uint32_t sbase = smem_u32(smem);
    const int tid = threadIdx.x;
    const int wid = tid >> 5;
    const int ln  = tid & 31;
    const int warp_m = wid >> 1;
    const int warp_n = wid & 1;
    const int m0 = blockIdx.y * GT_M;
    const int n0 = blockIdx.x * GT_N;

    float acc[2][8][4];
    #pragma unroll
    for (int i = 0; i < 2; i++)
        #pragma unroll
        for (int j = 0; j < 8; j++)
            #pragma unroll
            for (int q = 0; q < 4; q++) acc[i][j][q] = 0.0f;

    const int lrow = ln & 15;
    const int lhalf = ln >> 4;

    int a_row[2], b_row[4];
    #pragma unroll
    for (int mf = 0; mf < 2; mf++) a_row[mf] = warp_m * 32 + mf * 16 + lrow;
    #pragma unroll
    for (int nf = 0; nf < 4; nf++) b_row[nf] = warp_n * 64 + nf * 16 + lrow;

    // Loader geometry (fixed per thread)
    const int l_row = tid >> 1;           // 0..127 : two threads per row
    const int l_c   = (tid & 1) * 4;      // chunk 0..3 or 4..7

    auto issue_stage = [&](int kc, uint32_t stg) {
        const int k0 = kc * GT_K;
        #pragma unroll
        for (int cc = 0; cc < 4; cc++) {
            const int c = l_c + cc;
            const uint32_t so = SWZ128((uint32_t)(l_row * 128 + c * 16));
            const size_t ga = (size_t)(m0 + l_row) * GM_K + k0 + c * 8;
            const size_t gb = (size_t)(n0 + l_row) * GM_K + k0 + c * 8;
            cpasync16(sbase + stg + SM_AHI + so, Ahi + ga);
            cpasync16(sbase + stg + SM_ALO + so, Alo + ga);
            cpasync16(sbase + stg + SM_BHI + so, Bhi + gb);
            cpasync16(sbase + stg + SM_BLO + so, Blo + gb);
        }
        CP_COMMIT();
    };

    issue_stage(0, 0);

    for (int kc = 0; kc < GM_NK; kc++) {
        const uint32_t cur = (uint32_t)(kc & 1) * STG_B;
        if (kc + 1 < GM_NK) {
            issue_stage(kc + 1, (uint32_t)((kc + 1) & 1) * STG_B);
            CP_WAIT1();
        } else {
            CP_WAIT0();
        }
        __syncthreads();

        #pragma unroll
        for (int ks = 0; ks < 4; ks++) {
            const int chunk = ks * 2 + lhalf;
            uint32_t ah[2][4], al[2][4];
            #pragma unroll
            for (int mf = 0; mf < 2; mf++) {
                const int r = a_row[mf];
                const uint32_t off = (uint32_t)(r * 128 + ((chunk ^ (r & 7)) << 4));
                ldmx4(ah[mf], sbase + cur + SM_AHI + off);
                ldmx4(al[mf], sbase + cur + SM_ALO + off);
            }
            uint32_t bh[4][4], bl[4][4];
            #pragma unroll
            for (int nf = 0; nf < 4; nf++) {
                const int r = b_row[nf];
                const uint32_t off = (uint32_t)(r * 128 + ((chunk ^ (r & 7)) << 4));
                ldmx4(bh[nf], sbase + cur + SM_BHI + off);
                ldmx4(bl[nf], sbase + cur + SM_BLO + off);
            }
            #pragma unroll
            for (int mf = 0; mf < 2; mf++) {
                #pragma unroll
                for (int nf = 0; nf < 8; nf++) {
                    const int nfp = nf >> 1;
                    const int odd = nf & 1;
                    mma16816(acc[mf][nf], ah[mf], bh[nfp][odd], bh[nfp][2 + odd]);
                    mma16816(acc[mf][nf], ah[mf], bl[nfp][odd], bl[nfp][2 + odd]);
                    mma16816(acc[mf][nf], al[mf], bh[nfp][odd], bh[nfp][2 + odd]);
                }
            }
        }
        __syncthreads();
    }

    const int gid = ln >> 2;
    const int tig = ln & 3;
    #pragma unroll
    for (int mf = 0; mf < 2; mf++) {
        #pragma unroll
        for (int nf = 0; nf < 8; nf++) {
            const int col = n0 + warp_n * 64 + nf * 8 + tig * 2;
            const int r0 = m0 + warp_m * 32 + mf * 16 + gid;
            float2 v0, v1;
            v0.x = acc[mf][nf][0]; v0.y = acc[mf][nf][1];
            v1.x = acc[mf][nf][2]; v1.y = acc[mf][nf][3];
            if (SPLIT) {
                v0.x *= scale; v0.y *= scale; v1.x *= scale; v1.y *= scale;
                __nv_bfloat162 h0 = __float22bfloat162_rn(v0);
                __nv_bfloat162 h1 = __float22bfloat162_rn(v1);
                float2 r0v, r1v;
                r0v.x = v0.x - __bfloat162float(h0.x);
                r0v.y = v0.y - __bfloat162float(h0.y);
                r1v.x = v1.x - __bfloat162float(h1.x);
                r1v.y = v1.y - __bfloat162float(h1.y);
                __nv_bfloat162 l0b = __float22bfloat162_rn(r0v);
                __nv_bfloat162 l1b = __float22bfloat162_rn(r1v);
                *(__nv_bfloat162*)(Ohi + (size_t)r0 * GM_N + col) = h0;
                *(__nv_bfloat162*)(Olo + (size_t)r0 * GM_N + col) = l0b;
                *(__nv_bfloat162*)(Ohi + (size_t)(r0 + 8) * GM_N + col) = h1;
                *(__nv_bfloat162*)(Olo + (size_t)(r0 + 8) * GM_N + col) = l1b;
            } else {
                if (BIAS) {
                    const float b0v = bias[col], b1v = bias[col + 1];
                    v0.x += b0v; v0.y += b1v;
                    v1.x += b0v; v1.y += b1v;
                }
                *(float2*)(C + (size_t)r0 * GM_N + col) = v0;
                *(float2*)(C + (size_t)(r0 + 8) * GM_N + col) = v1;
            }
        }
    }
}

// ---------------------------------------------------------------------------
// Tensor-core flash attention, causal, bf16-split, work-balanced.
// Grid (16, 32): CTA x handles q-tiles {x, 31-x} of one (b,h) -> every CTA
// does exactly 33 k-tile iterations (load balance for causal mask).
// 4 warps x 16 q-rows; K/V tiles of 64 keys. Q pre-scaled by 1/sqrt(HD).
// ---------------------------------------------------------------------------
#define SF_QHI 0
#define SF_QLO 8192
#define SF_KHI 16384
#define SF_KLO 24576
#define SF_VHI 32768
#define SF_VLO 40960
#define SF_TOTAL 49152   // 48 KB

__global__ __launch_bounds__(128, 4) void flash_tc_kernel(
    const __nv_bfloat16* __restrict__ Qhi, const __nv_bfloat16* __restrict__ Qlo,
    const __nv_bfloat16* __restrict__ Khi, const __nv_bfloat16* __restrict__ Klo,
    const __nv_bfloat16* __restrict__ Vhi, const __nv_bfloat16* __restrict__ Vlo,
    __nv_bfloat16* __restrict__ Chi, __nv_bfloat16* __restrict__ Clo)
{
    extern __shared__ char smem[];
    const uint32_t sbase = smem_u32(smem);
    const int tid = threadIdx.x;
    const int wid = tid >> 5;
    const int ln  = tid & 31;
    const int b   = blockIdx.y >> 4;
    const int h   = blockIdx.y & 15;
    const size_t base = (size_t)b * MHA_S * MHA_D + (size_t)h * MHA_HD;

    const int lrow  = ln & 15;
    const int lhalf = ln >> 4;
    const int gid   = ln >> 2;
    const int tig   = ln & 3;
    const int arow  = wid * 16 + lrow;

    // cp.async loader geometry
    const int l_row = tid >> 1;
    const int l_c   = (tid & 1) * 4;

    #pragma unroll 1
    for (int pass = 0; pass < 2; pass++) {
        const int qt = pass ? (31 - (int)blockIdx.x) : (int)blockIdx.x;
        const int q0 = qt * 64;

        __syncthreads();   // previous pass fully done before Qs overwrite

        // Load Q tile (64 x 64 bf16, hi+lo)
        {
            const int r = l_row >> 1;                 // 0..63
            const int half = (l_row & 1);             // two loaders per row? no:
        }
        // 64 rows * 8 chunks = 512 chunks per tile; 128 threads -> 4 chunks each
        #pragma unroll
        for (int cc = 0; cc < 2; cc++) {
            const int id = cc * 128 + tid;            // 0..255
            const int r = id >> 2;                    // 0..63
            const int c = (id & 3) * 2;               // chunks 0,2,4,6
            #pragma unroll
            for (int s = 0; s < 2; s++) {
                const uint32_t so = SWZ128((uint32_t)(r * 128 + (c + s) * 16));
                const size_t g = base + (size_t)(q0 + r) * MHA_D + (c + s) * 8;
                cpasync16(sbase + SF_QHI + so, Qhi + g);
                cpasync16(sbase + SF_QLO + so, Qlo + g);
            }
        }
        CP_COMMIT();

        float m0 = -1e30f, m1 = -1e30f, l0 = 0.0f, l1 = 0.0f;
        float o[8][4];
        #pragma unroll
        for (int nf = 0; nf < 8; nf++)
            #pragma unroll
            for (int q = 0; q < 4; q++) o[nf][q] = 0.0f;

        const int row0 = q0 + wid * 16 + gid;
        const int row1 = row0 + 8;

        for (int kt = 0; kt <= qt; kt++) {
            const int k0 = kt * 64;
            __syncthreads();
            // K/V tiles: 4 x 512 chunks, 128 threads -> 4 chunks per tile each
            #pragma unroll
            for (int cc = 0; cc < 2; cc++) {
                const int id = cc * 128 + tid;
                const int r = id >> 2;
                const int c = (id & 3) * 2;
                #pragma unroll
                for (int s = 0; s < 2; s++) {
                    const uint32_t so = SWZ128((uint32_t)(r * 128 + (c + s) * 16));
                    const size_t g = base + (size_t)(k0 + r) * MHA_D + (c + s) * 8;
                    cpasync16(sbase + SF_KHI + so, Khi + g);
                    cpasync16(sbase + SF_KLO + so, Klo + g);
                    cpasync16(sbase + SF_VHI + so, Vhi + g);
                    cpasync16(sbase + SF_VLO + so, Vlo + g);
                }
            }
            CP_COMMIT();
            CP_WAIT0();
            __syncthreads();

            // ---- S = Q K^T ----
            float s[8][4];
            #pragma unroll
            for (int nf = 0; nf < 8; nf++)
                #pragma unroll
                for (int q = 0; q < 4; q++) s[nf][q] = 0.0f;

            #pragma unroll
            for (int ks = 0; ks < 4; ks++) {
                const int chunk = ks * 2 + lhalf;
                const uint32_t offA = (uint32_t)(arow * 128 + ((chunk ^ (arow & 7)) << 4));
                uint32_t ah[4], al[4];
                ldmx4(ah, sbase + SF_QHI + offA);
                ldmx4(al, sbase + SF_QLO + offA);
                #pragma unroll
                for (int nfp = 0; nfp < 4; nfp++) {
                    const int brow = nfp * 16 + lrow;
                    const uint32_t offB = (uint32_t)(brow * 128 + ((chunk ^ (brow & 7)) << 4));
                    uint32_t bh[4], bl[4];
                    ldmx4(bh, sbase + SF_KHI + offB);
                    ldmx4(bl, sbase + SF_KLO + offB);
                    #pragma unroll
                    for (int odd = 0; odd < 2; odd++) {
                        const int nf = nfp * 2 + odd;
                        mma16816(s[nf], ah, bh[odd], bh[2 + odd]);
                        mma16816(s[nf], ah, bl[odd], bl[2 + odd]);
                        mma16816(s[nf], al, bh[odd], bh[2 + odd]);
                    }
                }
            }

            // ---- causal mask (diagonal tile only) ----
            if (kt == qt) {
                #pragma unroll
                for (int nf = 0; nf < 8; nf++) {
                    const int c0 = k0 + nf * 8 + tig * 2;
                    if (c0 > row0)     s[nf][0] = -INFINITY;
                    if (c0 + 1 > row0) s[nf][1] = -INFINITY;
                    if (c0 > row1)     s[nf][2] = -INFINITY;
                    if (c0 + 1 > row1) s[nf][3] = -INFINITY;
                }
            }

            // ---- online softmax ----
            float mx0 = m0, mx1 = m1;
            #pragma unroll
            for (int nf = 0; nf < 8; nf++) {
                mx0 = fmaxf(mx0, fmaxf(s[nf][0], s[nf][1]));
                mx1 = fmaxf(mx1, fmaxf(s[nf][2], s[nf][3]));
            }
            mx0 = fmaxf(mx0, __shfl_xor_sync(0xffffffffu, mx0, 1));
            mx0 = fmaxf(mx0, __shfl_xor_sync(0xffffffffu, mx0, 2));
            mx1 = fmaxf(mx1, __shfl_xor_sync(0xffffffffu, mx1, 1));
            mx1 = fmaxf(mx1, __shfl_xor_sync(0xffffffffu, mx1, 2));

            const float corr0 = __expf(m0 - mx0);
            const float corr1 = __expf(m1 - mx1);
            m0 = mx0; m1 = mx1;

            float sum0 = 0.0f, sum1 = 0.0f;
            uint32_t ph[8][2], pl[8][2];
            #pragma unroll
            for (int nf = 0; nf < 8; nf++) {
                float2 p01, p23;
                p01.x = __expf(s[nf][0] - mx0);
                p01.y = __expf(s[nf][1] - mx0);
                p23.x = __expf(s[nf][2] - mx1);
                p23.y = __expf(s[nf][3] - mx1);
                sum0 += p01.x + p01.y;
                sum1 += p23.x + p23.y;
                __nv_bfloat162 h01 = __float22bfloat162_rn(p01);
                __nv_bfloat162 h23 = __float22bfloat162_rn(p23);
                float2 r01, r23;
                r01.x = p01.x - __bfloat162float(h01.x);
                r01.y = p01.y - __bfloat162float(h01.y);
                r23.x = p23.x - __bfloat162float(h23.x);
                r23.y = p23.y - __bfloat162float(h23.y);
                __nv_bfloat162 lo01 = __float22bfloat162_rn(r01);
                __nv_bfloat162 lo23 = __float22bfloat162_rn(r23);
                ph[nf][0] = *(uint32_t*)&h01;
                ph[nf][1] = *(uint32_t*)&h23;
                pl[nf][0] = *(uint32_t*)&lo01;
                pl[nf][1] = *(uint32_t*)&lo23;
            }
            sum0 += __shfl_xor_sync(0xffffffffu, sum0, 1);
            sum0 += __shfl_xor_sync(0xffffffffu, sum0, 2);
            sum1 += __shfl_xor_sync(0xffffffffu, sum1, 1);
            sum1 += __shfl_xor_sync(0xffffffffu, sum1, 2);
            l0 = l0 * corr0 + sum0;
            l1 = l1 * corr1 + sum1;

            #pragma unroll
            for (int nf = 0; nf < 8; nf++) {
                o[nf][0] *= corr0; o[nf][1] *= corr0;
                o[nf][2] *= corr1; o[nf][3] *= corr1;
            }

            // ---- O += P V ----
            #pragma unroll
            for (int kc = 0; kc < 4; kc++) {
                uint32_t aph[4], apl[4];
                aph[0] = ph[2 * kc][0];     aph[1] = ph[2 * kc][1];
                aph[2] = ph[2 * kc + 1][0]; aph[3] = ph[2 * kc + 1][1];
                apl[0] = pl[2 * kc][0];     apl[1] = pl[2 * kc][1];
                apl[2] = pl[2 * kc + 1][0]; apl[3] = pl[2 * kc + 1][1];
                const int g = ln >> 3;
                const int r8 = ln & 7;
                const int key = kc * 16 + (g & 1) * 8 + r8;
                #pragma unroll
                for (int hp = 0; hp < 4; hp++) {
                    const int chunk = hp * 2 + (g >> 1);
                    const uint32_t offV = (uint32_t)(key * 128 + ((chunk ^ (key & 7)) << 4));
                    uint32_t vh[4], vl[4];
                    ldmx4t(vh, sbase + SF_VHI + offV);
                    ldmx4t(vl, sbase + SF_VLO + offV);
                    mma16816(o[2 * hp], aph, vh[0], vh[1]);
                    mma16816(o[2 * hp], aph, vl[0], vl[1]);
                    mma16816(o[2 * hp], apl, vh[0], vh[1]);
                    mma16816(o[2 * hp + 1], aph, vh[2], vh[3]);
                    mma16816(o[2 * hp + 1], aph, vl[2], vl[3]);
                    mma16816(o[2 * hp + 1], apl, vh[2], vh[3]);
                }
            }
        }

        // ---- finalize and write ctx as bf16 hi/lo ----
        const float inv0 = 1.0f / l0;
        const float inv1 = 1.0f / l1;
        #pragma unroll
        for (int nf = 0; nf < 8; nf++) {
            const int col = nf * 8 + tig * 2;
            float2 v0, v1;
            v0.x = o[nf][0] * inv0; v0.y = o[nf][1] * inv0;
            v1.x = o[nf][2] * inv1; v1.y = o[nf][3] * inv1;
            __nv_bfloat162 h0 = __float22bfloat162_rn(v0);
            __nv_bfloat162 h1 = __float22bfloat162_rn(v1);
            float2 r0v, r1v;
            r0v.x = v0.x - __bfloat162float(h0.x);
            r0v.y = v0.y - __bfloat162float(h0.y);
            r1v.x = v1.x - __bfloat162float(h1.x);
            r1v.y = v1.y - __bfloat162float(h1.y);
            __nv_bfloat162 l0b = __float22bfloat162_rn(r0v);
            __nv_bfloat162 l1b = __float22bfloat162_rn(r1v);
            const size_t o0 = base + (size_t)row0 * MHA_D + col;
            const size_t o1 = base + (size_t)row1 * MHA_D + col;
            *(__nv_bfloat162*)(Chi + o0) = h0;
            *(__nv_bfloat162*)(Clo + o0) = l0b;
            *(__nv_bfloat162*)(Chi + o1) = h1;
            *(__nv_bfloat162*)(Clo + o1) = l1b;
        }
    }
}

// ---------------------------------------------------------------------------
extern "C" void kernel_launch(void* const* d_in, const int* in_sizes, int n_in,
                              void* d_out, int out_size)
{
    const float* x  = (const float*)d_in[0];
    const float* Wq = (const float*)d_in[1];
    const float* Wk = (const float*)d_in[2];
    const float* Wv = (const float*)d_in[3];
    const float* Wo = (const float*)d_in[4];
    const float* bo = (const float*)d_in[5];
    float* out = (float*)d_out;

    __nv_bfloat16 *xhi, *xlo;
    __nv_bfloat16 *qhi, *qlo, *khi, *klo, *vhi, *vlo, *chi, *clo;
    __nv_bfloat16 *wqh, *wql, *wkh, *wkl, *wvh, *wvl, *woh, *wol;
    cudaGetSymbolAddress((void**)&xhi, g_xhi);
    cudaGetSymbolAddress((void**)&xlo, g_xlo);
    cudaGetSymbolAddress((void**)&qhi, g_qhi);
    cudaGetSymbolAddress((void**)&qlo, g_qlo);
    cudaGetSymbolAddress((void**)&khi, g_khi);
    cudaGetSymbolAddress((void**)&klo, g_klo);
    cudaGetSymbolAddress((void**)&vhi, g_vhi);
    cudaGetSymbolAddress((void**)&vlo, g_vlo);
    cudaGetSymbolAddress((void**)&chi, g_chi);
    cudaGetSymbolAddress((void**)&clo, g_clo);
    cudaGetSymbolAddress((void**)&wqh, g_wqt_hi);
    cudaGetSymbolAddress((void**)&wql, g_wqt_lo);
    cudaGetSymbolAddress((void**)&wkh, g_wkt_hi);
    cudaGetSymbolAddress((void**)&wkl, g_wkt_lo);
    cudaGetSymbolAddress((void**)&wvh, g_wvt_hi);
    cudaGetSymbolAddress((void**)&wvl, g_wvt_lo);
    cudaGetSymbolAddress((void**)&woh, g_wot_hi);
    cudaGetSymbolAddress((void**)&wol, g_wot_lo);

    cudaFuncSetAttribute(flash_tc_kernel,
                         cudaFuncAttributeMaxDynamicSharedMemorySize, SF_TOTAL);
    cudaFuncSetAttribute(gemm_hmma_kernel<true, false>,
                         cudaFuncAttributeMaxDynamicSharedMemorySize, SM_GEMM_TOTAL);
    cudaFuncSetAttribute(gemm_hmma_kernel<false, true>,
                         cudaFuncAttributeMaxDynamicSharedMemorySize, SM_GEMM_TOTAL);

    // x -> bf16 hi/lo; weights -> transposed bf16 hi/lo
    split_kernel<<<NTOK * MHA_D / 1024, 256>>>(x, xhi, xlo);
    dim3 tgrid(MHA_D / 32, MHA_D / 32), tblk(32, 8);
    transpose_split_kernel<<<tgrid, tblk>>>(Wq, wqh, wql);
    transpose_split_kernel<<<tgrid, tblk>>>(Wk, wkh, wkl);
    transpose_split_kernel<<<tgrid, tblk>>>(Wv, wvh, wvl);
    transpose_split_kernel<<<tgrid, tblk>>>(Wo, woh, wol);

    // QKV projections -> split bf16 outputs (Q pre-scaled by 1/sqrt(HD))
    dim3 ggrid(GM_N / GT_N, GM_M / GT_M);
    gemm_hmma_kernel<true, false><<<ggrid, 256, SM_GEMM_TOTAL>>>(
        xhi, xlo, wqh, wql, nullptr, nullptr, qhi, qlo, 0.125f);
    gemm_hmma_kernel<true, false><<<ggrid, 256, SM_GEMM_TOTAL>>>(
        xhi, xlo, wkh, wkl, nullptr, nullptr, khi, klo, 1.0f);
    gemm_hmma_kernel<true, false><<<ggrid, 256, SM_GEMM_TOTAL>>>(
        xhi, xlo, wvh, wvl, nullptr, nullptr, vhi, vlo, 1.0f);

    // Balanced tensor-core causal flash attention -> split bf16 ctx
    dim3 fa_grid(MHA_S / 128, MHA_B * MHA_H);   // (16, 32)
    flash_tc_kernel<<<fa_grid, 128, SF_TOTAL>>>(qhi, qlo, khi, klo, vhi, vlo, chi, clo);

    // Output projection with bias (fp32 out)
    gemm_hmma_kernel<false, true><<<ggrid, 256, SM_GEMM_TOTAL>>>(
        chi, clo, woh, wol, bo, out, nullptr, nullptr, 1.0f);
}

// round 9
// speedup vs baseline: 1.0133x; 1.0133x over previous
#include <cuda_runtime.h>
#include <cuda_bf16.h>
#include <math.h>
#include <stdint.h>

#define MHA_B  2
#define MHA_S  2048
#define MHA_D  1024
#define MHA_H  16
#define MHA_HD 64
#define NTOK   (MHA_B * MHA_S)

// ---------------------------------------------------------------------------
// Scratch (__device__ globals; allocation-free rule)
// ---------------------------------------------------------------------------
__device__ __nv_bfloat16 g_xhi[NTOK * MHA_D];
__device__ __nv_bfloat16 g_xlo[NTOK * MHA_D];

__device__ __nv_bfloat16 g_qhi[NTOK * MHA_D];
__device__ __nv_bfloat16 g_qlo[NTOK * MHA_D];
__device__ __nv_bfloat16 g_khi[NTOK * MHA_D];
__device__ __nv_bfloat16 g_klo[NTOK * MHA_D];
__device__ __nv_bfloat16 g_vhi[NTOK * MHA_D];
__device__ __nv_bfloat16 g_vlo[NTOK * MHA_D];
__device__ __nv_bfloat16 g_chi[NTOK * MHA_D];
__device__ __nv_bfloat16 g_clo[NTOK * MHA_D];

__device__ __nv_bfloat16 g_wqt_hi[MHA_D * MHA_D];
__device__ __nv_bfloat16 g_wqt_lo[MHA_D * MHA_D];
__device__ __nv_bfloat16 g_wkt_hi[MHA_D * MHA_D];
__device__ __nv_bfloat16 g_wkt_lo[MHA_D * MHA_D];
__device__ __nv_bfloat16 g_wvt_hi[MHA_D * MHA_D];
__device__ __nv_bfloat16 g_wvt_lo[MHA_D * MHA_D];
__device__ __nv_bfloat16 g_wot_hi[MHA_D * MHA_D];
__device__ __nv_bfloat16 g_wot_lo[MHA_D * MHA_D];

// ---------------------------------------------------------------------------
// Portable (sm_80+) tensor-core + async-copy helpers
// ---------------------------------------------------------------------------
__device__ __forceinline__ uint32_t smem_u32(const void* p) {
    uint32_t a;
    asm("{ .reg .u64 t; cvta.to.shared.u64 t, %1; cvt.u32.u64 %0, t; }"
        : "=r"(a) : "l"(p));
    return a;
}

__device__ __forceinline__ void ldmx4(uint32_t* r, uint32_t addr) {
    asm volatile(
        "ldmatrix.sync.aligned.m8n8.x4.shared.b16 {%0,%1,%2,%3}, [%4];"
        : "=r"(r[0]), "=r"(r[1]), "=r"(r[2]), "=r"(r[3]) : "r"(addr));
}

__device__ __forceinline__ void ldmx4t(uint32_t* r, uint32_t addr) {
    asm volatile(
        "ldmatrix.sync.aligned.m8n8.x4.trans.shared.b16 {%0,%1,%2,%3}, [%4];"
        : "=r"(r[0]), "=r"(r[1]), "=r"(r[2]), "=r"(r[3]) : "r"(addr));
}

__device__ __forceinline__ void mma16816(float* d, const uint32_t* a,
                                         uint32_t b0, uint32_t b1) {
    asm volatile(
        "mma.sync.aligned.m16n8k16.row.col.f32.bf16.bf16.f32 "
        "{%0,%1,%2,%3}, {%4,%5,%6,%7}, {%8,%9}, {%0,%1,%2,%3};"
        : "+f"(d[0]), "+f"(d[1]), "+f"(d[2]), "+f"(d[3])
        : "r"(a[0]), "r"(a[1]), "r"(a[2]), "r"(a[3]), "r"(b0), "r"(b1));
}

__device__ __forceinline__ void cpasync16(uint32_t saddr, const void* gaddr) {
    asm volatile("cp.async.cg.shared.global [%0], [%1], 16;"
                 :: "r"(saddr), "l"(gaddr));
}
#define CP_COMMIT() asm volatile("cp.async.commit_group;" ::: "memory")
#define CP_WAIT0()  asm volatile("cp.async.wait_group 0;" ::: "memory")
#define CP_WAIT1()  asm volatile("cp.async.wait_group 1;" ::: "memory")

#define SWZ128(off) ((off) ^ (((off) >> 3) & 0x70))

// ---------------------------------------------------------------------------
// Conversion kernels
// ---------------------------------------------------------------------------
__global__ void split_kernel(const float* __restrict__ in,
                             __nv_bfloat16* __restrict__ hi,
                             __nv_bfloat16* __restrict__ lo)
{
    int i = (blockIdx.x * 256 + threadIdx.x) * 4;
    float4 v = *(const float4*)(in + i);
    __nv_bfloat16 h0 = __float2bfloat16(v.x);
    __nv_bfloat16 h1 = __float2bfloat16(v.y);
    __nv_bfloat16 h2 = __float2bfloat16(v.z);
    __nv_bfloat16 h3 = __float2bfloat16(v.w);
    __nv_bfloat16 l0 = __float2bfloat16(v.x - __bfloat162float(h0));
    __nv_bfloat16 l1 = __float2bfloat16(v.y - __bfloat162float(h1));
    __nv_bfloat16 l2 = __float2bfloat16(v.z - __bfloat162float(h2));
    __nv_bfloat16 l3 = __float2bfloat16(v.w - __bfloat162float(h3));
    ((__nv_bfloat162*)hi)[i / 2]     = __nv_bfloat162(h0, h1);
    ((__nv_bfloat162*)hi)[i / 2 + 1] = __nv_bfloat162(h2, h3);
    ((__nv_bfloat162*)lo)[i / 2]     = __nv_bfloat162(l0, l1);
    ((__nv_bfloat162*)lo)[i / 2 + 1] = __nv_bfloat162(l2, l3);
}

// Batched: transposes+splits all 4 weight matrices in one launch (blockIdx.z)
__global__ void transpose_split4_kernel(
    const float* __restrict__ W0, const float* __restrict__ W1,
    const float* __restrict__ W2, const float* __restrict__ W3,
    __nv_bfloat16* __restrict__ T0h, __nv_bfloat16* __restrict__ T0l,
    __nv_bfloat16* __restrict__ T1h, __nv_bfloat16* __restrict__ T1l,
    __nv_bfloat16* __restrict__ T2h, __nv_bfloat16* __restrict__ T2l,
    __nv_bfloat16* __restrict__ T3h, __nv_bfloat16* __restrict__ T3l)
{
    const float* W;
    __nv_bfloat16 *Th, *Tl;
    switch (blockIdx.z) {
        case 0: W = W0; Th = T0h; Tl = T0l; break;
        case 1: W = W1; Th = T1h; Tl = T1l; break;
        case 2: W = W2; Th = T2h; Tl = T2l; break;
        default: W = W3; Th = T3h; Tl = T3l; break;
    }
    __shared__ float t[32][33];
    const int tx = threadIdx.x, ty = threadIdx.y;
    const int k0 = blockIdx.y * 32;
    const int n0 = blockIdx.x * 32;
    #pragma unroll
    for (int j = 0; j < 4; j++)
        t[ty + j * 8][tx] = W[(size_t)(k0 + ty + j * 8) * MHA_D + n0 + tx];
    __syncthreads();
    #pragma unroll
    for (int j = 0; j < 4; j++) {
        float v = t[tx][ty + j * 8];
        __nv_bfloat16 h = __float2bfloat16(v);
        __nv_bfloat16 l = __float2bfloat16(v - __bfloat162float(h));
        size_t o = (size_t)(n0 + ty + j * 8) * MHA_D + k0 + tx;
        Th[o] = h;
        Tl[o] = l;
    }
}

// ---------------------------------------------------------------------------
// HMMA bf16-split GEMM, cp.async double-buffered.
// ---------------------------------------------------------------------------
#define GM_M 4096
#define GM_N 1024
#define GM_K 1024
#define GT_M 128
#define GT_N 128
#define GT_K 64
#define GM_NK (GM_K / GT_K)

#define TILE_B (GT_M * GT_K * 2)
#define SM_AHI 0
#define SM_ALO TILE_B
#define SM_BHI (2 * TILE_B)
#define SM_BLO (3 * TILE_B)
#define STG_B  (4 * TILE_B)
#define SM_GEMM_TOTAL (2 * STG_B)   // 128 KB

template <bool SPLIT, bool BIAS>
__global__ __launch_bounds__(256, 1) void gemm_hmma_kernel(
    const __nv_bfloat16* __restrict__ Ahi, const __nv_bfloat16* __restrict__ Alo,
    const __nv_bfloat16* __restrict__ Bhi, const __nv_bfloat16* __restrict__ Blo,
    const float* __restrict__ bias, float* __restrict__ C,
    __nv_bfloat16* __restrict__ Ohi, __nv_bfloat16* __restrict__ Olo,
    float scale)
{
    extern __shared__ char smem[];
    const uint32_t sbase = smem_u32(smem);
    const int tid = threadIdx.x;
    const int wid = tid >> 5;
    const int ln  = tid & 31;
    const int warp_m = wid >> 1;
    const int warp_n = wid & 1;
    const int m0 = blockIdx.y * GT_M;
    const int n0 = blockIdx.x * GT_N;

    float acc[2][8][4];
    #pragma unroll
    for (int i = 0; i < 2; i++)
        #pragma unroll
        for (int j = 0; j < 8; j++)
            #pragma unroll
            for (int q = 0; q < 4; q++) acc[i][j][q] = 0.0f;

    const int lrow = ln & 15;
    const int lhalf = ln >> 4;

    int a_row[2], b_row[4];
    #pragma unroll
    for (int mf = 0; mf < 2; mf++) a_row[mf] = warp_m * 32 + mf * 16 + lrow;
    #pragma unroll
    for (int nf = 0; nf < 4; nf++) b_row[nf] = warp_n * 64 + nf * 16 + lrow;

    const int l_row = tid >> 1;
    const int l_c   = (tid & 1) * 4;

    auto issue_stage = [&](int kc, uint32_t stg) {
        const int k0 = kc * GT_K;
        #pragma unroll
        for (int cc = 0; cc < 4; cc++) {
            const int c = l_c + cc;
            const uint32_t so = SWZ128((uint32_t)(l_row * 128 + c * 16));
            const size_t ga = (size_t)(m0 + l_row) * GM_K + k0 + c * 8;
            const size_t gb = (size_t)(n0 + l_row) * GM_K + k0 + c * 8;
            cpasync16(sbase + stg + SM_AHI + so, Ahi + ga);
            cpasync16(sbase + stg + SM_ALO + so, Alo + ga);
            cpasync16(sbase + stg + SM_BHI + so, Bhi + gb);
            cpasync16(sbase + stg + SM_BLO + so, Blo + gb);
        }
        CP_COMMIT();
    };

    issue_stage(0, 0);

    for (int kc = 0; kc < GM_NK; kc++) {
        const uint32_t cur = (uint32_t)(kc & 1) * STG_B;
        if (kc + 1 < GM_NK) {
            issue_stage(kc + 1, (uint32_t)((kc + 1) & 1) * STG_B);
            CP_WAIT1();
        } else {
            CP_WAIT0();
        }
        __syncthreads();

        #pragma unroll
        for (int ks = 0; ks < 4; ks++) {
            const int chunk = ks * 2 + lhalf;
            uint32_t ah[2][4], al[2][4];
            #pragma unroll
            for (int mf = 0; mf < 2; mf++) {
                const int r = a_row[mf];
                const uint32_t off = (uint32_t)(r * 128 + ((chunk ^ (r & 7)) << 4));
                ldmx4(ah[mf], sbase + cur + SM_AHI + off);
                ldmx4(al[mf], sbase + cur + SM_ALO + off);
            }
            uint32_t bh[4][4], bl[4][4];
            #pragma unroll
            for (int nf = 0; nf < 4; nf++) {
                const int r = b_row[nf];
                const uint32_t off = (uint32_t)(r * 128 + ((chunk ^ (r & 7)) << 4));
                ldmx4(bh[nf], sbase + cur + SM_BHI + off);
                ldmx4(bl[nf], sbase + cur + SM_BLO + off);
            }
            #pragma unroll
            for (int mf = 0; mf < 2; mf++) {
                #pragma unroll
                for (int nf = 0; nf < 8; nf++) {
                    const int nfp = nf >> 1;
                    const int odd = nf & 1;
                    mma16816(acc[mf][nf], ah[mf], bh[nfp][odd], bh[nfp][2 + odd]);
                    mma16816(acc[mf][nf], ah[mf], bl[nfp][odd], bl[nfp][2 + odd]);
                    mma16816(acc[mf][nf], al[mf], bh[nfp][odd], bh[nfp][2 + odd]);
                }
            }
        }
        __syncthreads();
    }

    const int gid = ln >> 2;
    const int tig = ln & 3;
    #pragma unroll
    for (int mf = 0; mf < 2; mf++) {
        #pragma unroll
        for (int nf = 0; nf < 8; nf++) {
            const int col = n0 + warp_n * 64 + nf * 8 + tig * 2;
            const int r0 = m0 + warp_m * 32 + mf * 16 + gid;
            float2 v0, v1;
            v0.x = acc[mf][nf][0]; v0.y = acc[mf][nf][1];
            v1.x = acc[mf][nf][2]; v1.y = acc[mf][nf][3];
            if (SPLIT) {
                v0.x *= scale; v0.y *= scale; v1.x *= scale; v1.y *= scale;
                __nv_bfloat162 h0 = __float22bfloat162_rn(v0);
                __nv_bfloat162 h1 = __float22bfloat162_rn(v1);
                float2 r0v, r1v;
                r0v.x = v0.x - __bfloat162float(h0.x);
                r0v.y = v0.y - __bfloat162float(h0.y);
                r1v.x = v1.x - __bfloat162float(h1.x);
                r1v.y = v1.y - __bfloat162float(h1.y);
                __nv_bfloat162 l0b = __float22bfloat162_rn(r0v);
                __nv_bfloat162 l1b = __float22bfloat162_rn(r1v);
                *(__nv_bfloat162*)(Ohi + (size_t)r0 * GM_N + col) = h0;
                *(__nv_bfloat162*)(Olo + (size_t)r0 * GM_N + col) = l0b;
                *(__nv_bfloat162*)(Ohi + (size_t)(r0 + 8) * GM_N + col) = h1;
                *(__nv_bfloat162*)(Olo + (size_t)(r0 + 8) * GM_N + col) = l1b;
            } else {
                if (BIAS) {
                    const float b0v = bias[col], b1v = bias[col + 1];
                    v0.x += b0v; v0.y += b1v;
                    v1.x += b0v; v1.y += b1v;
                }
                *(float2*)(C + (size_t)r0 * GM_N + col) = v0;
                *(float2*)(C + (size_t)(r0 + 8) * GM_N + col) = v1;
            }
        }
    }
}

// ---------------------------------------------------------------------------
// Tensor-core flash attention v3 (fixed coverage): causal, bf16-split,
// 128-query tiles, 2-stage pipelined K/V loads, pair-balanced.
// Grid (8, 32), 256 threads (8 warps x 16 q-rows). 16 q-tiles of 128 rows;
// CTA x handles q-tiles {x, 15-x} -> exactly 34 k-tile iterations per CTA.
// ---------------------------------------------------------------------------
#define SFQ_HI 0
#define SFQ_LO 16384
#define SFS_BASE 32768
#define SFS_SZ 32768
#define SFK_HI 0
#define SFK_LO 8192
#define SFV_HI 16384
#define SFV_LO 24576
#define SF_TOTAL (SFS_BASE + 2 * SFS_SZ)   // 96 KB

__global__ __launch_bounds__(256, 1) void flash_tc_kernel(
    const __nv_bfloat16* __restrict__ Qhi, const __nv_bfloat16* __restrict__ Qlo,
    const __nv_bfloat16* __restrict__ Khi, const __nv_bfloat16* __restrict__ Klo,
    const __nv_bfloat16* __restrict__ Vhi, const __nv_bfloat16* __restrict__ Vlo,
    __nv_bfloat16* __restrict__ Chi, __nv_bfloat16* __restrict__ Clo)
{
    extern __shared__ char smem[];
    const uint32_t sbase = smem_u32(smem);
    const int tid = threadIdx.x;
    const int wid = tid >> 5;
    const int ln  = tid & 31;
    const int b   = blockIdx.y >> 4;
    const int h   = blockIdx.y & 15;
    const size_t base = (size_t)b * MHA_S * MHA_D + (size_t)h * MHA_HD;

    const int lrow  = ln & 15;
    const int lhalf = ln >> 4;
    const int gid   = ln >> 2;
    const int tig   = ln & 3;
    const int arow  = wid * 16 + lrow;   // 0..127

    auto load_q = [&](int q0) {
        #pragma unroll
        for (int cc = 0; cc < 4; cc++) {
            const int id = cc * 256 + tid;         // 0..1023
            const int r = id >> 3;                 // 0..127
            const int c = id & 7;
            const uint32_t so = SWZ128((uint32_t)(r * 128 + c * 16));
            const size_t g = base + (size_t)(q0 + r) * MHA_D + c * 8;
            cpasync16(sbase + SFQ_HI + so, Qhi + g);
            cpasync16(sbase + SFQ_LO + so, Qlo + g);
        }
    };
    auto load_kv = [&](int k0, uint32_t stg) {
        #pragma unroll
        for (int cc = 0; cc < 2; cc++) {
            const int id = cc * 256 + tid;         // 0..511
            const int r = id >> 3;                 // 0..63
            const int c = id & 7;
            const uint32_t so = SWZ128((uint32_t)(r * 128 + c * 16));
            const size_t g = base + (size_t)(k0 + r) * MHA_D + c * 8;
            cpasync16(sbase + stg + SFK_HI + so, Khi + g);
            cpasync16(sbase + stg + SFK_LO + so, Klo + g);
            cpasync16(sbase + stg + SFV_HI + so, Vhi + g);
            cpasync16(sbase + stg + SFV_LO + so, Vlo + g);
        }
        CP_COMMIT();
    };

    #pragma unroll 1
    for (int pass = 0; pass < 2; pass++) {
        const int qt = pass ? (15 - (int)blockIdx.x) : (int)blockIdx.x;
        const int q0 = qt * 128;
        const int ktmax = 2 * qt + 1;

        __syncthreads();   // previous pass fully done before smem reuse

        load_q(q0);
        load_kv(0, SFS_BASE);   // group 1 = Q + kv stage0

        float m0 = -1e30f, m1 = -1e30f, l0 = 0.0f, l1 = 0.0f;
        float o[8][4];
        #pragma unroll
        for (int nf = 0; nf < 8; nf++)
            #pragma unroll
            for (int q = 0; q < 4; q++) o[nf][q] = 0.0f;

        const int row0 = q0 + wid * 16 + gid;
        const int row1 = row0 + 8;

        for (int kt = 0; kt <= ktmax; kt++) {
            const int k0 = kt * 64;
            const uint32_t cur = SFS_BASE + (uint32_t)(kt & 1) * SFS_SZ;
            if (kt < ktmax) {
                load_kv((kt + 1) * 64, SFS_BASE + (uint32_t)((kt + 1) & 1) * SFS_SZ);
                CP_WAIT1();
            } else {
                CP_WAIT0();
            }
            __syncthreads();

            // ---- S = Q K^T ----
            float s[8][4];
            #pragma unroll
            for (int nf = 0; nf < 8; nf++)
                #pragma unroll
                for (int q = 0; q < 4; q++) s[nf][q] = 0.0f;

            #pragma unroll
            for (int ks = 0; ks < 4; ks++) {
                const int chunk = ks * 2 + lhalf;
                const uint32_t offA = (uint32_t)(arow * 128 + ((chunk ^ (arow & 7)) << 4));
                uint32_t ah[4], al[4];
                ldmx4(ah, sbase + SFQ_HI + offA);
                ldmx4(al, sbase + SFQ_LO + offA);
                #pragma unroll
                for (int nfp = 0; nfp < 4; nfp++) {
                    const int brow = nfp * 16 + lrow;
                    const uint32_t offB = (uint32_t)(brow * 128 + ((chunk ^ (brow & 7)) << 4));
                    uint32_t bh[4], bl[4];
                    ldmx4(bh, sbase + cur + SFK_HI + offB);
                    ldmx4(bl, sbase + cur + SFK_LO + offB);
                    #pragma unroll
                    for (int odd = 0; odd < 2; odd++) {
                        const int nf = nfp * 2 + odd;
                        mma16816(s[nf], ah, bh[odd], bh[2 + odd]);
                        mma16816(s[nf], ah, bl[odd], bl[2 + odd]);
                        mma16816(s[nf], al, bh[odd], bh[2 + odd]);
                    }
                }
            }

            // ---- causal mask (only the last two k-tiles can cross diag) ----
            if (kt >= 2 * qt) {
                #pragma unroll
                for (int nf = 0; nf < 8; nf++) {
                    const int c0 = k0 + nf * 8 + tig * 2;
                    if (c0 > row0)     s[nf][0] = -INFINITY;
                    if (c0 + 1 > row0) s[nf][1] = -INFINITY;
                    if (c0 > row1)     s[nf][2] = -INFINITY;
                    if (c0 + 1 > row1) s[nf][3] = -INFINITY;
                }
            }

            // ---- online softmax ----
            float mx0 = m0, mx1 = m1;
            #pragma unroll
            for (int nf = 0; nf < 8; nf++) {
                mx0 = fmaxf(mx0, fmaxf(s[nf][0], s[nf][1]));
                mx1 = fmaxf(mx1, fmaxf(s[nf][2], s[nf][3]));
            }
            mx0 = fmaxf(mx0, __shfl_xor_sync(0xffffffffu, mx0, 1));
            mx0 = fmaxf(mx0, __shfl_xor_sync(0xffffffffu, mx0, 2));
            mx1 = fmaxf(mx1, __shfl_xor_sync(0xffffffffu, mx1, 1));
            mx1 = fmaxf(mx1, __shfl_xor_sync(0xffffffffu, mx1, 2));

            const float corr0 = __expf(m0 - mx0);
            const float corr1 = __expf(m1 - mx1);
            m0 = mx0; m1 = mx1;

            float sum0 = 0.0f, sum1 = 0.0f;
            uint32_t ph[8][2], pl[8][2];
            #pragma unroll
            for (int nf = 0; nf < 8; nf++) {
                float2 p01, p23;
                p01.x = __expf(s[nf][0] - mx0);
                p01.y = __expf(s[nf][1] - mx0);
                p23.x = __expf(s[nf][2] - mx1);
                p23.y = __expf(s[nf][3] - mx1);
                sum0 += p01.x + p01.y;
                sum1 += p23.x + p23.y;
                __nv_bfloat162 h01 = __float22bfloat162_rn(p01);
                __nv_bfloat162 h23 = __float22bfloat162_rn(p23);
                float2 r01, r23;
                r01.x = p01.x - __bfloat162float(h01.x);
                r01.y = p01.y - __bfloat162float(h01.y);
                r23.x = p23.x - __bfloat162float(h23.x);
                r23.y = p23.y - __bfloat162float(h23.y);
                __nv_bfloat162 lo01 = __float22bfloat162_rn(r01);
                __nv_bfloat162 lo23 = __float22bfloat162_rn(r23);
                ph[nf][0] = *(uint32_t*)&h01;
                ph[nf][1] = *(uint32_t*)&h23;
                pl[nf][0] = *(uint32_t*)&lo01;
                pl[nf][1] = *(uint32_t*)&lo23;
            }
            sum0 += __shfl_xor_sync(0xffffffffu, sum0, 1);
            sum0 += __shfl_xor_sync(0xffffffffu, sum0, 2);
            sum1 += __shfl_xor_sync(0xffffffffu, sum1, 1);
            sum1 += __shfl_xor_sync(0xffffffffu, sum1, 2);
            l0 = l0 * corr0 + sum0;
            l1 = l1 * corr1 + sum1;

            #pragma unroll
            for (int nf = 0; nf < 8; nf++) {
                o[nf][0] *= corr0; o[nf][1] *= corr0;
                o[nf][2] *= corr1; o[nf][3] *= corr1;
            }

            // ---- O += P V ----
            #pragma unroll
            for (int kc = 0; kc < 4; kc++) {
                uint32_t aph[4], apl[4];
                aph[0] = ph[2 * kc][0];     aph[1] = ph[2 * kc][1];
                aph[2] = ph[2 * kc + 1][0]; aph[3] = ph[2 * kc + 1][1];
                apl[0] = pl[2 * kc][0];     apl[1] = pl[2 * kc][1];
                apl[2] = pl[2 * kc + 1][0]; apl[3] = pl[2 * kc + 1][1];
                const int g = ln >> 3;
                const int r8 = ln & 7;
                const int key = kc * 16 + (g & 1) * 8 + r8;
                #pragma unroll
                for (int hp = 0; hp < 4; hp++) {
                    const int chunk = hp * 2 + (g >> 1);
                    const uint32_t offV = (uint32_t)(key * 128 + ((chunk ^ (key & 7)) << 4));
                    uint32_t vh[4], vl[4];
                    ldmx4t(vh, sbase + cur + SFV_HI + offV);
                    ldmx4t(vl, sbase + cur + SFV_LO + offV);
                    mma16816(o[2 * hp], aph, vh[0], vh[1]);
                    mma16816(o[2 * hp], aph, vl[0], vl[1]);
                    mma16816(o[2 * hp], apl, vh[0], vh[1]);
                    mma16816(o[2 * hp + 1], aph, vh[2], vh[3]);
                    mma16816(o[2 * hp + 1], aph, vl[2], vl[3]);
                    mma16816(o[2 * hp + 1], apl, vh[2], vh[3]);
                }
            }
            __syncthreads();   // all warps done with `cur` before next prefetch
        }

        // ---- finalize and write ctx as bf16 hi/lo ----
        const float inv0 = 1.0f / l0;
        const float inv1 = 1.0f / l1;
        #pragma unroll
        for (int nf = 0; nf < 8; nf++) {
            const int col = nf * 8 + tig * 2;
            float2 v0, v1;
            v0.x = o[nf][0] * inv0; v0.y = o[nf][1] * inv0;
            v1.x = o[nf][2] * inv1; v1.y = o[nf][3] * inv1;
            __nv_bfloat162 h0 = __float22bfloat162_rn(v0);
            __nv_bfloat162 h1 = __float22bfloat162_rn(v1);
            float2 r0v, r1v;
            r0v.x = v0.x - __bfloat162float(h0.x);
            r0v.y = v0.y - __bfloat162float(h0.y);
            r1v.x = v1.x - __bfloat162float(h1.x);
            r1v.y = v1.y - __bfloat162float(h1.y);
            __nv_bfloat162 l0b = __float22bfloat162_rn(r0v);
            __nv_bfloat162 l1b = __float22bfloat162_rn(r1v);
            const size_t o0 = base + (size_t)row0 * MHA_D + col;
            const size_t o1 = base + (size_t)row1 * MHA_D + col;
            *(__nv_bfloat162*)(Chi + o0) = h0;
            *(__nv_bfloat162*)(Clo + o0) = l0b;
            *(__nv_bfloat162*)(Chi + o1) = h1;
            *(__nv_bfloat162*)(Clo + o1) = l1b;
        }
    }
}

// ---------------------------------------------------------------------------
extern "C" void kernel_launch(void* const* d_in, const int* in_sizes, int n_in,
                              void* d_out, int out_size)
{
    const float* x  = (const float*)d_in[0];
    const float* Wq = (const float*)d_in[1];
    const float* Wk = (const float*)d_in[2];
    const float* Wv = (const float*)d_in[3];
    const float* Wo = (const float*)d_in[4];
    const float* bo = (const float*)d_in[5];
    float* out = (float*)d_out;

    __nv_bfloat16 *xhi, *xlo;
    __nv_bfloat16 *qhi, *qlo, *khi, *klo, *vhi, *vlo, *chi, *clo;
    __nv_bfloat16 *wqh, *wql, *wkh, *wkl, *wvh, *wvl, *woh, *wol;
    cudaGetSymbolAddress((void**)&xhi, g_xhi);
    cudaGetSymbolAddress((void**)&xlo, g_xlo);
    cudaGetSymbolAddress((void**)&qhi, g_qhi);
    cudaGetSymbolAddress((void**)&qlo, g_qlo);
    cudaGetSymbolAddress((void**)&khi, g_khi);
    cudaGetSymbolAddress((void**)&klo, g_klo);
    cudaGetSymbolAddress((void**)&vhi, g_vhi);
    cudaGetSymbolAddress((void**)&vlo, g_vlo);
    cudaGetSymbolAddress((void**)&chi, g_chi);
    cudaGetSymbolAddress((void**)&clo, g_clo);
    cudaGetSymbolAddress((void**)&wqh, g_wqt_hi);
    cudaGetSymbolAddress((void**)&wql, g_wqt_lo);
    cudaGetSymbolAddress((void**)&wkh, g_wkt_hi);
    cudaGetSymbolAddress((void**)&wkl, g_wkt_lo);
    cudaGetSymbolAddress((void**)&wvh, g_wvt_hi);
    cudaGetSymbolAddress((void**)&wvl, g_wvt_lo);
    cudaGetSymbolAddress((void**)&woh, g_wot_hi);
    cudaGetSymbolAddress((void**)&wol, g_wot_lo);

    cudaFuncSetAttribute(flash_tc_kernel,
                         cudaFuncAttributeMaxDynamicSharedMemorySize, SF_TOTAL);
    cudaFuncSetAttribute(gemm_hmma_kernel<true, false>,
                         cudaFuncAttributeMaxDynamicSharedMemorySize, SM_GEMM_TOTAL);
    cudaFuncSetAttribute(gemm_hmma_kernel<false, true>,
                         cudaFuncAttributeMaxDynamicSharedMemorySize, SM_GEMM_TOTAL);

    // 1) x -> bf16 hi/lo
    split_kernel<<<NTOK * MHA_D / 1024, 256>>>(x, xhi, xlo);
    // 2) all four weights -> transposed bf16 hi/lo (one launch)
    dim3 tgrid(MHA_D / 32, MHA_D / 32, 4), tblk(32, 8);
    transpose_split4_kernel<<<tgrid, tblk>>>(Wq, Wk, Wv, Wo,
                                             wqh, wql, wkh, wkl,
                                             wvh, wvl, woh, wol);

    // 3-5) QKV projections -> split bf16 (Q pre-scaled by 1/sqrt(HD))
    dim3 ggrid(GM_N / GT_N, GM_M / GT_M);
    gemm_hmma_kernel<true, false><<<ggrid, 256, SM_GEMM_TOTAL>>>(
        xhi, xlo, wqh, wql, nullptr, nullptr, qhi, qlo, 0.125f);
    gemm_hmma_kernel<true, false><<<ggrid, 256, SM_GEMM_TOTAL>>>(
        xhi, xlo, wkh, wkl, nullptr, nullptr, khi, klo, 1.0f);
    gemm_hmma_kernel<true, false><<<ggrid, 256, SM_GEMM_TOTAL>>>(
        xhi, xlo, wvh, wvl, nullptr, nullptr, vhi, vlo, 1.0f);

    // 6) Pipelined balanced tensor-core causal flash -> split bf16 ctx
    dim3 fa_grid(MHA_S / 256, MHA_B * MHA_H);   // (8, 32): 16 q-tiles, pairs {x,15-x}
    flash_tc_kernel<<<fa_grid, 256, SF_TOTAL>>>(qhi, qlo, khi, klo, vhi, vlo, chi, clo);

    // 7) Output projection with bias (fp32 out)
    gemm_hmma_kernel<false, true><<<ggrid, 256, SM_GEMM_TOTAL>>>(
        chi, clo, woh, wol, bo, out, nullptr, nullptr, 1.0f);
}

// round 11
// speedup vs baseline: 1.1366x; 1.1216x over previous
#include <cuda_runtime.h>
#include <cuda_bf16.h>
#include <math.h>
#include <stdint.h>

#define MHA_B  2
#define MHA_S  2048
#define MHA_D  1024
#define MHA_H  16
#define MHA_HD 64
#define NTOK   (MHA_B * MHA_S)

// ---------------------------------------------------------------------------
// Scratch (__device__ globals; allocation-free rule)
// ---------------------------------------------------------------------------
__device__ __nv_bfloat16 g_xhi[NTOK * MHA_D];
__device__ __nv_bfloat16 g_xlo[NTOK * MHA_D];

__device__ __nv_bfloat16 g_qhi[NTOK * MHA_D];
__device__ __nv_bfloat16 g_qlo[NTOK * MHA_D];
__device__ __nv_bfloat16 g_khi[NTOK * MHA_D];
__device__ __nv_bfloat16 g_klo[NTOK * MHA_D];
__device__ __nv_bfloat16 g_vhi[NTOK * MHA_D];
__device__ __nv_bfloat16 g_vlo[NTOK * MHA_D];
__device__ __nv_bfloat16 g_chi[NTOK * MHA_D];
__device__ __nv_bfloat16 g_clo[NTOK * MHA_D];

__device__ __nv_bfloat16 g_wqt_hi[MHA_D * MHA_D];
__device__ __nv_bfloat16 g_wqt_lo[MHA_D * MHA_D];
__device__ __nv_bfloat16 g_wkt_hi[MHA_D * MHA_D];
__device__ __nv_bfloat16 g_wkt_lo[MHA_D * MHA_D];
__device__ __nv_bfloat16 g_wvt_hi[MHA_D * MHA_D];
__device__ __nv_bfloat16 g_wvt_lo[MHA_D * MHA_D];
__device__ __nv_bfloat16 g_wot_hi[MHA_D * MHA_D];
__device__ __nv_bfloat16 g_wot_lo[MHA_D * MHA_D];

// ---------------------------------------------------------------------------
// Portable (sm_80+) tensor-core + async-copy helpers
// ---------------------------------------------------------------------------
__device__ __forceinline__ uint32_t smem_u32(const void* p) {
    uint32_t a;
    asm("{ .reg .u64 t; cvta.to.shared.u64 t, %1; cvt.u32.u64 %0, t; }"
        : "=r"(a) : "l"(p));
    return a;
}

__device__ __forceinline__ void ldmx4(uint32_t* r, uint32_t addr) {
    asm volatile(
        "ldmatrix.sync.aligned.m8n8.x4.shared.b16 {%0,%1,%2,%3}, [%4];"
        : "=r"(r[0]), "=r"(r[1]), "=r"(r[2]), "=r"(r[3]) : "r"(addr));
}

__device__ __forceinline__ void ldmx4t(uint32_t* r, uint32_t addr) {
    asm volatile(
        "ldmatrix.sync.aligned.m8n8.x4.trans.shared.b16 {%0,%1,%2,%3}, [%4];"
        : "=r"(r[0]), "=r"(r[1]), "=r"(r[2]), "=r"(r[3]) : "r"(addr));
}

__device__ __forceinline__ void mma16816(float* d, const uint32_t* a,
                                         uint32_t b0, uint32_t b1) {
    asm volatile(
        "mma.sync.aligned.m16n8k16.row.col.f32.bf16.bf16.f32 "
        "{%0,%1,%2,%3}, {%4,%5,%6,%7}, {%8,%9}, {%0,%1,%2,%3};"
        : "+f"(d[0]), "+f"(d[1]), "+f"(d[2]), "+f"(d[3])
        : "r"(a[0]), "r"(a[1]), "r"(a[2]), "r"(a[3]), "r"(b0), "r"(b1));
}

__device__ __forceinline__ void cpasync16(uint32_t saddr, const void* gaddr) {
    asm volatile("cp.async.cg.shared.global [%0], [%1], 16;"
                 :: "r"(saddr), "l"(gaddr));
}
#define CP_COMMIT() asm volatile("cp.async.commit_group;" ::: "memory")
#define CP_WAIT0()  asm volatile("cp.async.wait_group 0;" ::: "memory")
#define CP_WAIT1()  asm volatile("cp.async.wait_group 1;" ::: "memory")

#define SWZ128(off) ((off) ^ (((off) >> 3) & 0x70))

// ---------------------------------------------------------------------------
// Conversion kernels
// ---------------------------------------------------------------------------
__global__ void split_kernel(const float* __restrict__ in,
                             __nv_bfloat16* __restrict__ hi,
                             __nv_bfloat16* __restrict__ lo)
{
    int i = (blockIdx.x * 256 + threadIdx.x) * 4;
    float4 v = *(const float4*)(in + i);
    __nv_bfloat16 h0 = __float2bfloat16(v.x);
    __nv_bfloat16 h1 = __float2bfloat16(v.y);
    __nv_bfloat16 h2 = __float2bfloat16(v.z);
    __nv_bfloat16 h3 = __float2bfloat16(v.w);
    __nv_bfloat16 l0 = __float2bfloat16(v.x - __bfloat162float(h0));
    __nv_bfloat16 l1 = __float2bfloat16(v.y - __bfloat162float(h1));
    __nv_bfloat16 l2 = __float2bfloat16(v.z - __bfloat162float(h2));
    __nv_bfloat16 l3 = __float2bfloat16(v.w - __bfloat162float(h3));
    ((__nv_bfloat162*)hi)[i / 2]     = __nv_bfloat162(h0, h1);
    ((__nv_bfloat162*)hi)[i / 2 + 1] = __nv_bfloat162(h2, h3);
    ((__nv_bfloat162*)lo)[i / 2]     = __nv_bfloat162(l0, l1);
    ((__nv_bfloat162*)lo)[i / 2 + 1] = __nv_bfloat162(l2, l3);
}

// Batched: transposes+splits all 4 weight matrices in one launch (blockIdx.z)
__global__ void transpose_split4_kernel(
    const float* __restrict__ W0, const float* __restrict__ W1,
    const float* __restrict__ W2, const float* __restrict__ W3,
    __nv_bfloat16* __restrict__ T0h, __nv_bfloat16* __restrict__ T0l,
    __nv_bfloat16* __restrict__ T1h, __nv_bfloat16* __restrict__ T1l,
    __nv_bfloat16* __restrict__ T2h, __nv_bfloat16* __restrict__ T2l,
    __nv_bfloat16* __restrict__ T3h, __nv_bfloat16* __restrict__ T3l)
{
    const float* W;
    __nv_bfloat16 *Th, *Tl;
    switch (blockIdx.z) {
        case 0: W = W0; Th = T0h; Tl = T0l; break;
        case 1: W = W1; Th = T1h; Tl = T1l; break;
        case 2: W = W2; Th = T2h; Tl = T2l; break;
        default: W = W3; Th = T3h; Tl = T3l; break;
    }
    __shared__ float t[32][33];
    const int tx = threadIdx.x, ty = threadIdx.y;
    const int k0 = blockIdx.y * 32;
    const int n0 = blockIdx.x * 32;
    #pragma unroll
    for (int j = 0; j < 4; j++)
        t[ty + j * 8][tx] = W[(size_t)(k0 + ty + j * 8) * MHA_D + n0 + tx];
    __syncthreads();
    #pragma unroll
    for (int j = 0; j < 4; j++) {
        float v = t[tx][ty + j * 8];
        __nv_bfloat16 h = __float2bfloat16(v);
        __nv_bfloat16 l = __float2bfloat16(v - __bfloat162float(h));
        size_t o = (size_t)(n0 + ty + j * 8) * MHA_D + k0 + tx;
        Th[o] = h;
        Tl[o] = l;
    }
}

// ---------------------------------------------------------------------------
// HMMA bf16-split GEMM, cp.async double-buffered, 512 threads / 16 warps.
// CTA: 128x128 tile, BK=64. Warps 4(m)x4(n); warp tile 32x32.
// 4 warps per SMSP (occupancy fix for issue-starvation at 2 warps/SMSP).
// ---------------------------------------------------------------------------
#define GM_M 4096
#define GM_N 1024
#define GM_K 1024
#define GT_M 128
#define GT_N 128
#define GT_K 64
#define GM_NK (GM_K / GT_K)

#define TILE_B (GT_M * GT_K * 2)
#define SM_AHI 0
#define SM_ALO TILE_B
#define SM_BHI (2 * TILE_B)
#define SM_BLO (3 * TILE_B)
#define STG_B  (4 * TILE_B)
#define SM_GEMM_TOTAL (2 * STG_B)   // 128 KB

template <bool SPLIT, bool BIAS>
__global__ __launch_bounds__(512, 1) void gemm_hmma_kernel(
    const __nv_bfloat16* __restrict__ Ahi, const __nv_bfloat16* __restrict__ Alo,
    const __nv_bfloat16* __restrict__ Bhi, const __nv_bfloat16* __restrict__ Blo,
    const float* __restrict__ bias, float* __restrict__ C,
    __nv_bfloat16* __restrict__ Ohi, __nv_bfloat16* __restrict__ Olo,
    float scale)
{
    extern __shared__ char smem[];
    const uint32_t sbase = smem_u32(smem);
    const int tid = threadIdx.x;
    const int wid = tid >> 5;
    const int ln  = tid & 31;
    const int warp_m = wid >> 2;        // 0..3 (32 rows each)
    const int warp_n = wid & 3;         // 0..3 (32 cols each)
    const int m0 = blockIdx.y * GT_M;
    const int n0 = blockIdx.x * GT_N;

    float acc[2][4][4];
    #pragma unroll
    for (int i = 0; i < 2; i++)
        #pragma unroll
        for (int j = 0; j < 4; j++)
            #pragma unroll
            for (int q = 0; q < 4; q++) acc[i][j][q] = 0.0f;

    const int lrow = ln & 15;
    const int lhalf = ln >> 4;

    int a_row[2], b_row[2];
    #pragma unroll
    for (int mf = 0; mf < 2; mf++) a_row[mf] = warp_m * 32 + mf * 16 + lrow;
    #pragma unroll
    for (int nfp = 0; nfp < 2; nfp++) b_row[nfp] = warp_n * 32 + nfp * 16 + lrow;

    // Loader geometry: stage = 4 tiles x 1024 chunks; 512 threads x 2 chunks/tile
    const int l_row = tid >> 2;          // 0..127
    const int l_c   = (tid & 3) * 2;     // chunks {0,2,4,6}

    auto issue_stage = [&](int kc, uint32_t stg) {
        const int k0 = kc * GT_K;
        #pragma unroll
        for (int cc = 0; cc < 2; cc++) {
            const int c = l_c + cc;
            const uint32_t so = SWZ128((uint32_t)(l_row * 128 + c * 16));
            const size_t ga = (size_t)(m0 + l_row) * GM_K + k0 + c * 8;
            const size_t gb = (size_t)(n0 + l_row) * GM_K + k0 + c * 8;
            cpasync16(sbase + stg + SM_AHI + so, Ahi + ga);
            cpasync16(sbase + stg + SM_ALO + so, Alo + ga);
            cpasync16(sbase + stg + SM_BHI + so, Bhi + gb);
            cpasync16(sbase + stg + SM_BLO + so, Blo + gb);
        }
        CP_COMMIT();
    };

    issue_stage(0, 0);

    for (int kc = 0; kc < GM_NK; kc++) {
        const uint32_t cur = (uint32_t)(kc & 1) * STG_B;
        if (kc + 1 < GM_NK) {
            issue_stage(kc + 1, (uint32_t)((kc + 1) & 1) * STG_B);
            CP_WAIT1();
        } else {
            CP_WAIT0();
        }
        __syncthreads();

        #pragma unroll
        for (int ks = 0; ks < 4; ks++) {
            const int chunk = ks * 2 + lhalf;
            uint32_t ah[2][4], al[2][4];
            #pragma unroll
            for (int mf = 0; mf < 2; mf++) {
                const int r = a_row[mf];
                const uint32_t off = (uint32_t)(r * 128 + ((chunk ^ (r & 7)) << 4));
                ldmx4(ah[mf], sbase + cur + SM_AHI + off);
                ldmx4(al[mf], sbase + cur + SM_ALO + off);
            }
            uint32_t bh[2][4], bl[2][4];
            #pragma unroll
            for (int nfp = 0; nfp < 2; nfp++) {
                const int r = b_row[nfp];
                const uint32_t off = (uint32_t)(r * 128 + ((chunk ^ (r & 7)) << 4));
                ldmx4(bh[nfp], sbase + cur + SM_BHI + off);
                ldmx4(bl[nfp], sbase + cur + SM_BLO + off);
            }
            #pragma unroll
            for (int mf = 0; mf < 2; mf++) {
                #pragma unroll
                for (int nf = 0; nf < 4; nf++) {
                    const int nfp = nf >> 1;
                    const int odd = nf & 1;
                    mma16816(acc[mf][nf], ah[mf], bh[nfp][odd], bh[nfp][2 + odd]);
                    mma16816(acc[mf][nf], ah[mf], bl[nfp][odd], bl[nfp][2 + odd]);
                    mma16816(acc[mf][nf], al[mf], bh[nfp][odd], bh[nfp][2 + odd]);
                }
            }
        }
        __syncthreads();
    }

    const int gid = ln >> 2;
    const int tig = ln & 3;
    #pragma unroll
    for (int mf = 0; mf < 2; mf++) {
        #pragma unroll
        for (int nf = 0; nf < 4; nf++) {
            const int col = n0 + warp_n * 32 + nf * 8 + tig * 2;
            const int r0 = m0 + warp_m * 32 + mf * 16 + gid;
            float2 v0, v1;
            v0.x = acc[mf][nf][0]; v0.y = acc[mf][nf][1];
            v1.x = acc[mf][nf][2]; v1.y = acc[mf][nf][3];
            if (SPLIT) {
                v0.x *= scale; v0.y *= scale; v1.x *= scale; v1.y *= scale;
                __nv_bfloat162 h0 = __float22bfloat162_rn(v0);
                __nv_bfloat162 h1 = __float22bfloat162_rn(v1);
                float2 r0v, r1v;
                r0v.x = v0.x - __bfloat162float(h0.x);
                r0v.y = v0.y - __bfloat162float(h0.y);
                r1v.x = v1.x - __bfloat162float(h1.x);
                r1v.y = v1.y - __bfloat162float(h1.y);
                __nv_bfloat162 l0b = __float22bfloat162_rn(r0v);
                __nv_bfloat162 l1b = __float22bfloat162_rn(r1v);
                *(__nv_bfloat162*)(Ohi + (size_t)r0 * GM_N + col) = h0;
                *(__nv_bfloat162*)(Olo + (size_t)r0 * GM_N + col) = l0b;
                *(__nv_bfloat162*)(Ohi + (size_t)(r0 + 8) * GM_N + col) = h1;
                *(__nv_bfloat162*)(Olo + (size_t)(r0 + 8) * GM_N + col) = l1b;
            } else {
                if (BIAS) {
                    const float b0v = bias[col], b1v = bias[col + 1];
                    v0.x += b0v; v0.y += b1v;
                    v1.x += b0v; v1.y += b1v;
                }
                *(float2*)(C + (size_t)r0 * GM_N + col) = v0;
                *(float2*)(C + (size_t)(r0 + 8) * GM_N + col) = v1;
            }
        }
    }
}

// ---------------------------------------------------------------------------
// Tensor-core flash attention (unchanged from R9 pass): causal, bf16-split,
// 128-query tiles, 2-stage pipelined K/V, pair-balanced.
// Grid (8, 32), 256 threads. CTA x handles q-tiles {x, 15-x} -> 34 iters.
// ---------------------------------------------------------------------------
#define SFQ_HI 0
#define SFQ_LO 16384
#define SFS_BASE 32768
#define SFS_SZ 32768
#define SFK_HI 0
#define SFK_LO 8192
#define SFV_HI 16384
#define SFV_LO 24576
#define SF_TOTAL (SFS_BASE + 2 * SFS_SZ)   // 96 KB

__global__ __launch_bounds__(256, 1) void flash_tc_kernel(
    const __nv_bfloat16* __restrict__ Qhi, const __nv_bfloat16* __restrict__ Qlo,
    const __nv_bfloat16* __restrict__ Khi, const __nv_bfloat16* __restrict__ Klo,
    const __nv_bfloat16* __restrict__ Vhi, const __nv_bfloat16* __restrict__ Vlo,
    __nv_bfloat16* __restrict__ Chi, __nv_bfloat16* __restrict__ Clo)
{
    extern __shared__ char smem[];
    const uint32_t sbase = smem_u32(smem);
    const int tid = threadIdx.x;
    const int wid = tid >> 5;
    const int ln  = tid & 31;
    const int b   = blockIdx.y >> 4;
    const int h   = blockIdx.y & 15;
    const size_t base = (size_t)b * MHA_S * MHA_D + (size_t)h * MHA_HD;

    const int lrow  = ln & 15;
    const int lhalf = ln >> 4;
    const int gid   = ln >> 2;
    const int tig   = ln & 3;
    const int arow  = wid * 16 + lrow;   // 0..127

    auto load_q = [&](int q0) {
        #pragma unroll
        for (int cc = 0; cc < 4; cc++) {
            const int id = cc * 256 + tid;         // 0..1023
            const int r = id >> 3;                 // 0..127
            const int c = id & 7;
            const uint32_t so = SWZ128((uint32_t)(r * 128 + c * 16));
            const size_t g = base + (size_t)(q0 + r) * MHA_D + c * 8;
            cpasync16(sbase + SFQ_HI + so, Qhi + g);
            cpasync16(sbase + SFQ_LO + so, Qlo + g);
        }
    };
    auto load_kv = [&](int k0, uint32_t stg) {
        #pragma unroll
        for (int cc = 0; cc < 2; cc++) {
            const int id = cc * 256 + tid;         // 0..511
            const int r = id >> 3;                 // 0..63
            const int c = id & 7;
            const uint32_t so = SWZ128((uint32_t)(r * 128 + c * 16));
            const size_t g = base + (size_t)(k0 + r) * MHA_D + c * 8;
            cpasync16(sbase + stg + SFK_HI + so, Khi + g);
            cpasync16(sbase + stg + SFK_LO + so, Klo + g);
            cpasync16(sbase + stg + SFV_HI + so, Vhi + g);
            cpasync16(sbase + stg + SFV_LO + so, Vlo + g);
        }
        CP_COMMIT();
    };

    #pragma unroll 1
    for (int pass = 0; pass < 2; pass++) {
        const int qt = pass ? (15 - (int)blockIdx.x) : (int)blockIdx.x;
        const int q0 = qt * 128;
        const int ktmax = 2 * qt + 1;

        __syncthreads();   // previous pass fully done before smem reuse

        load_q(q0);
        load_kv(0, SFS_BASE);   // group 1 = Q + kv stage0

        float m0 = -1e30f, m1 = -1e30f, l0 = 0.0f, l1 = 0.0f;
        float o[8][4];
        #pragma unroll
        for (int nf = 0; nf < 8; nf++)
            #pragma unroll
            for (int q = 0; q < 4; q++) o[nf][q] = 0.0f;

        const int row0 = q0 + wid * 16 + gid;
        const int row1 = row0 + 8;

        for (int kt = 0; kt <= ktmax; kt++) {
            const int k0 = kt * 64;
            const uint32_t cur = SFS_BASE + (uint32_t)(kt & 1) * SFS_SZ;
            if (kt < ktmax) {
                load_kv((kt + 1) * 64, SFS_BASE + (uint32_t)((kt + 1) & 1) * SFS_SZ);
                CP_WAIT1();
            } else {
                CP_WAIT0();
            }
            __syncthreads();

            // ---- S = Q K^T ----
            float s[8][4];
            #pragma unroll
            for (int nf = 0; nf < 8; nf++)
                #pragma unroll
                for (int q = 0; q < 4; q++) s[nf][q] = 0.0f;

            #pragma unroll
            for (int ks = 0; ks < 4; ks++) {
                const int chunk = ks * 2 + lhalf;
                const uint32_t offA = (uint32_t)(arow * 128 + ((chunk ^ (arow & 7)) << 4));
                uint32_t ah[4], al[4];
                ldmx4(ah, sbase + SFQ_HI + offA);
                ldmx4(al, sbase + SFQ_LO + offA);
                #pragma unroll
                for (int nfp = 0; nfp < 4; nfp++) {
                    const int brow = nfp * 16 + lrow;
                    const uint32_t offB = (uint32_t)(brow * 128 + ((chunk ^ (brow & 7)) << 4));
                    uint32_t bh[4], bl[4];
                    ldmx4(bh, sbase + cur + SFK_HI + offB);
                    ldmx4(bl, sbase + cur + SFK_LO + offB);
                    #pragma unroll
                    for (int odd = 0; odd < 2; odd++) {
                        const int nf = nfp * 2 + odd;
                        mma16816(s[nf], ah, bh[odd], bh[2 + odd]);
                        mma16816(s[nf], ah, bl[odd], bl[2 + odd]);
                        mma16816(s[nf], al, bh[odd], bh[2 + odd]);
                    }
                }
            }

            // ---- causal mask (only the last two k-tiles can cross diag) ----
            if (kt >= 2 * qt) {
                #pragma unroll
                for (int nf = 0; nf < 8; nf++) {
                    const int c0 = k0 + nf * 8 + tig * 2;
                    if (c0 > row0)     s[nf][0] = -INFINITY;
                    if (c0 + 1 > row0) s[nf][1] = -INFINITY;
                    if (c0 > row1)     s[nf][2] = -INFINITY;
                    if (c0 + 1 > row1) s[nf][3] = -INFINITY;
                }
            }

            // ---- online softmax ----
            float mx0 = m0, mx1 = m1;
            #pragma unroll
            for (int nf = 0; nf < 8; nf++) {
                mx0 = fmaxf(mx0, fmaxf(s[nf][0], s[nf][1]));
                mx1 = fmaxf(mx1, fmaxf(s[nf][2], s[nf][3]));
            }
            mx0 = fmaxf(mx0, __shfl_xor_sync(0xffffffffu, mx0, 1));
            mx0 = fmaxf(mx0, __shfl_xor_sync(0xffffffffu, mx0, 2));
            mx1 = fmaxf(mx1, __shfl_xor_sync(0xffffffffu, mx1, 1));
            mx1 = fmaxf(mx1, __shfl_xor_sync(0xffffffffu, mx1, 2));

            const float corr0 = __expf(m0 - mx0);
            const float corr1 = __expf(m1 - mx1);
            m0 = mx0; m1 = mx1;

            float sum0 = 0.0f, sum1 = 0.0f;
            uint32_t ph[8][2], pl[8][2];
            #pragma unroll
            for (int nf = 0; nf < 8; nf++) {
                float2 p01, p23;
                p01.x = __expf(s[nf][0] - mx0);
                p01.y = __expf(s[nf][1] - mx0);
                p23.x = __expf(s[nf][2] - mx1);
                p23.y = __expf(s[nf][3] - mx1);
                sum0 += p01.x + p01.y;
                sum1 += p23.x + p23.y;
                __nv_bfloat162 h01 = __float22bfloat162_rn(p01);
                __nv_bfloat162 h23 = __float22bfloat162_rn(p23);
                float2 r01, r23;
                r01.x = p01.x - __bfloat162float(h01.x);
                r01.y = p01.y - __bfloat162float(h01.y);
                r23.x = p23.x - __bfloat162float(h23.x);
                r23.y = p23.y - __bfloat162float(h23.y);
                __nv_bfloat162 lo01 = __float22bfloat162_rn(r01);
                __nv_bfloat162 lo23 = __float22bfloat162_rn(r23);
                ph[nf][0] = *(uint32_t*)&h01;
                ph[nf][1] = *(uint32_t*)&h23;
                pl[nf][0] = *(uint32_t*)&lo01;
                pl[nf][1] = *(uint32_t*)&lo23;
            }
            sum0 += __shfl_xor_sync(0xffffffffu, sum0, 1);
            sum0 += __shfl_xor_sync(0xffffffffu, sum0, 2);
            sum1 += __shfl_xor_sync(0xffffffffu, sum1, 1);
            sum1 += __shfl_xor_sync(0xffffffffu, sum1, 2);
            l0 = l0 * corr0 + sum0;
            l1 = l1 * corr1 + sum1;

            #pragma unroll
            for (int nf = 0; nf < 8; nf++) {
                o[nf][0] *= corr0; o[nf][1] *= corr0;
                o[nf][2] *= corr1; o[nf][3] *= corr1;
            }

            // ---- O += P V ----
            #pragma unroll
            for (int kc = 0; kc < 4; kc++) {
                uint32_t aph[4], apl[4];
                aph[0] = ph[2 * kc][0];     aph[1] = ph[2 * kc][1];
                aph[2] = ph[2 * kc + 1][0]; aph[3] = ph[2 * kc + 1][1];
                apl[0] = pl[2 * kc][0];     apl[1] = pl[2 * kc][1];
                apl[2] = pl[2 * kc + 1][0]; apl[3] = pl[2 * kc + 1][1];
                const int g = ln >> 3;
                const int r8 = ln & 7;
                const int key = kc * 16 + (g & 1) * 8 + r8;
                #pragma unroll
                for (int hp = 0; hp < 4; hp++) {
                    const int chunk = hp * 2 + (g >> 1);
                    const uint32_t offV = (uint32_t)(key * 128 + ((chunk ^ (key & 7)) << 4));
                    uint32_t vh[4], vl[4];
                    ldmx4t(vh, sbase + cur + SFV_HI + offV);
                    ldmx4t(vl, sbase + cur + SFV_LO + offV);
                    mma16816(o[2 * hp], aph, vh[0], vh[1]);
                    mma16816(o[2 * hp], aph, vl[0], vl[1]);
                    mma16816(o[2 * hp], apl, vh[0], vh[1]);
                    mma16816(o[2 * hp + 1], aph, vh[2], vh[3]);
                    mma16816(o[2 * hp + 1], aph, vl[2], vl[3]);
                    mma16816(o[2 * hp + 1], apl, vh[2], vh[3]);
                }
            }
            __syncthreads();   // all warps done with `cur` before next prefetch
        }

        // ---- finalize and write ctx as bf16 hi/lo ----
        const float inv0 = 1.0f / l0;
        const float inv1 = 1.0f / l1;
        #pragma unroll
        for (int nf = 0; nf < 8; nf++) {
            const int col = nf * 8 + tig * 2;
            float2 v0, v1;
            v0.x = o[nf][0] * inv0; v0.y = o[nf][1] * inv0;
            v1.x = o[nf][2] * inv1; v1.y = o[nf][3] * inv1;
            __nv_bfloat162 h0 = __float22bfloat162_rn(v0);
            __nv_bfloat162 h1 = __float22bfloat162_rn(v1);
            float2 r0v, r1v;
            r0v.x = v0.x - __bfloat162float(h0.x);
            r0v.y = v0.y - __bfloat162float(h0.y);
            r1v.x = v1.x - __bfloat162float(h1.x);
            r1v.y = v1.y - __bfloat162float(h1.y);
            __nv_bfloat162 l0b = __float22bfloat162_rn(r0v);
            __nv_bfloat162 l1b = __float22bfloat162_rn(r1v);
            const size_t o0 = base + (size_t)row0 * MHA_D + col;
            const size_t o1 = base + (size_t)row1 * MHA_D + col;
            *(__nv_bfloat162*)(Chi + o0) = h0;
            *(__nv_bfloat162*)(Clo + o0) = l0b;
            *(__nv_bfloat162*)(Chi + o1) = h1;
            *(__nv_bfloat162*)(Clo + o1) = l1b;
        }
    }
}

// ---------------------------------------------------------------------------
extern "C" void kernel_launch(void* const* d_in, const int* in_sizes, int n_in,
                              void* d_out, int out_size)
{
    const float* x  = (const float*)d_in[0];
    const float* Wq = (const float*)d_in[1];
    const float* Wk = (const float*)d_in[2];
    const float* Wv = (const float*)d_in[3];
    const float* Wo = (const float*)d_in[4];
    const float* bo = (const float*)d_in[5];
    float* out = (float*)d_out;

    __nv_bfloat16 *xhi, *xlo;
    __nv_bfloat16 *qhi, *qlo, *khi, *klo, *vhi, *vlo, *chi, *clo;
    __nv_bfloat16 *wqh, *wql, *wkh, *wkl, *wvh, *wvl, *woh, *wol;
    cudaGetSymbolAddress((void**)&xhi, g_xhi);
    cudaGetSymbolAddress((void**)&xlo, g_xlo);
    cudaGetSymbolAddress((void**)&qhi, g_qhi);
    cudaGetSymbolAddress((void**)&qlo, g_qlo);
    cudaGetSymbolAddress((void**)&khi, g_khi);
    cudaGetSymbolAddress((void**)&klo, g_klo);
    cudaGetSymbolAddress((void**)&vhi, g_vhi);
    cudaGetSymbolAddress((void**)&vlo, g_vlo);
    cudaGetSymbolAddress((void**)&chi, g_chi);
    cudaGetSymbolAddress((void**)&clo, g_clo);
    cudaGetSymbolAddress((void**)&wqh, g_wqt_hi);
    cudaGetSymbolAddress((void**)&wql, g_wqt_lo);
    cudaGetSymbolAddress((void**)&wkh, g_wkt_hi);
    cudaGetSymbolAddress((void**)&wkl, g_wkt_lo);
    cudaGetSymbolAddress((void**)&wvh, g_wvt_hi);
    cudaGetSymbolAddress((void**)&wvl, g_wvt_lo);
    cudaGetSymbolAddress((void**)&woh, g_wot_hi);
    cudaGetSymbolAddress((void**)&wol, g_wot_lo);

    cudaFuncSetAttribute(flash_tc_kernel,
                         cudaFuncAttributeMaxDynamicSharedMemorySize, SF_TOTAL);
    cudaFuncSetAttribute(gemm_hmma_kernel<true, false>,
                         cudaFuncAttributeMaxDynamicSharedMemorySize, SM_GEMM_TOTAL);
    cudaFuncSetAttribute(gemm_hmma_kernel<false, true>,
                         cudaFuncAttributeMaxDynamicSharedMemorySize, SM_GEMM_TOTAL);

    // 1) x -> bf16 hi/lo
    split_kernel<<<NTOK * MHA_D / 1024, 256>>>(x, xhi, xlo);
    // 2) all four weights -> transposed bf16 hi/lo (one launch)
    dim3 tgrid(MHA_D / 32, MHA_D / 32, 4), tblk(32, 8);
    transpose_split4_kernel<<<tgrid, tblk>>>(Wq, Wk, Wv, Wo,
                                             wqh, wql, wkh, wkl,
                                             wvh, wvl, woh, wol);

    // 3-5) QKV projections -> split bf16 (Q pre-scaled by 1/sqrt(HD))
    dim3 ggrid(GM_N / GT_N, GM_M / GT_M);  // (8, 32)
    gemm_hmma_kernel<true, false><<<ggrid, 512, SM_GEMM_TOTAL>>>(
        xhi, xlo, wqh, wql, nullptr, nullptr, qhi, qlo, 0.125f);
    gemm_hmma_kernel<true, false><<<ggrid, 512, SM_GEMM_TOTAL>>>(
        xhi, xlo, wkh, wkl, nullptr, nullptr, khi, klo, 1.0f);
    gemm_hmma_kernel<true, false><<<ggrid, 512, SM_GEMM_TOTAL>>>(
        xhi, xlo, wvh, wvl, nullptr, nullptr, vhi, vlo, 1.0f);

    // 6) Pipelined balanced tensor-core causal flash -> split bf16 ctx
    dim3 fa_grid(MHA_S / 256, MHA_B * MHA_H);   // (8, 32)
    flash_tc_kernel<<<fa_grid, 256, SF_TOTAL>>>(qhi, qlo, khi, klo, vhi, vlo, chi, clo);

    // 7) Output projection with bias (fp32 out)
    gemm_hmma_kernel<false, true><<<ggrid, 512, SM_GEMM_TOTAL>>>(
        chi, clo, woh, wol, bo, out, nullptr, nullptr, 1.0f);
}

// round 12
// speedup vs baseline: 1.2537x; 1.1031x over previous
#include <cuda_runtime.h>
#include <cuda_bf16.h>
#include <math.h>
#include <stdint.h>

#define MHA_B  2
#define MHA_S  2048
#define MHA_D  1024
#define MHA_H  16
#define MHA_HD 64
#define NTOK   (MHA_B * MHA_S)

// ---------------------------------------------------------------------------
// Scratch (__device__ globals; allocation-free rule)
// ---------------------------------------------------------------------------
__device__ __nv_bfloat16 g_xhi[NTOK * MHA_D];
__device__ __nv_bfloat16 g_xlo[NTOK * MHA_D];

__device__ __nv_bfloat16 g_qhi[NTOK * MHA_D];
__device__ __nv_bfloat16 g_qlo[NTOK * MHA_D];
__device__ __nv_bfloat16 g_khi[NTOK * MHA_D];
__device__ __nv_bfloat16 g_klo[NTOK * MHA_D];
__device__ __nv_bfloat16 g_vhi[NTOK * MHA_D];
__device__ __nv_bfloat16 g_vlo[NTOK * MHA_D];
__device__ __nv_bfloat16 g_chi[NTOK * MHA_D];
__device__ __nv_bfloat16 g_clo[NTOK * MHA_D];

__device__ __nv_bfloat16 g_wqt_hi[MHA_D * MHA_D];
__device__ __nv_bfloat16 g_wqt_lo[MHA_D * MHA_D];
__device__ __nv_bfloat16 g_wkt_hi[MHA_D * MHA_D];
__device__ __nv_bfloat16 g_wkt_lo[MHA_D * MHA_D];
__device__ __nv_bfloat16 g_wvt_hi[MHA_D * MHA_D];
__device__ __nv_bfloat16 g_wvt_lo[MHA_D * MHA_D];
__device__ __nv_bfloat16 g_wot_hi[MHA_D * MHA_D];
__device__ __nv_bfloat16 g_wot_lo[MHA_D * MHA_D];

// ---------------------------------------------------------------------------
// Portable (sm_80+) tensor-core + async-copy helpers
// ---------------------------------------------------------------------------
__device__ __forceinline__ uint32_t smem_u32(const void* p) {
    uint32_t a;
    asm("{ .reg .u64 t; cvta.to.shared.u64 t, %1; cvt.u32.u64 %0, t; }"
        : "=r"(a) : "l"(p));
    return a;
}

__device__ __forceinline__ void ldmx4(uint32_t* r, uint32_t addr) {
    asm volatile(
        "ldmatrix.sync.aligned.m8n8.x4.shared.b16 {%0,%1,%2,%3}, [%4];"
        : "=r"(r[0]), "=r"(r[1]), "=r"(r[2]), "=r"(r[3]) : "r"(addr));
}

__device__ __forceinline__ void ldmx4t(uint32_t* r, uint32_t addr) {
    asm volatile(
        "ldmatrix.sync.aligned.m8n8.x4.trans.shared.b16 {%0,%1,%2,%3}, [%4];"
        : "=r"(r[0]), "=r"(r[1]), "=r"(r[2]), "=r"(r[3]) : "r"(addr));
}

__device__ __forceinline__ void mma16816(float* d, const uint32_t* a,
                                         uint32_t b0, uint32_t b1) {
    asm volatile(
        "mma.sync.aligned.m16n8k16.row.col.f32.bf16.bf16.f32 "
        "{%0,%1,%2,%3}, {%4,%5,%6,%7}, {%8,%9}, {%0,%1,%2,%3};"
        : "+f"(d[0]), "+f"(d[1]), "+f"(d[2]), "+f"(d[3])
        : "r"(a[0]), "r"(a[1]), "r"(a[2]), "r"(a[3]), "r"(b0), "r"(b1));
}

__device__ __forceinline__ void cpasync16(uint32_t saddr, const void* gaddr) {
    asm volatile("cp.async.cg.shared.global [%0], [%1], 16;"
                 :: "r"(saddr), "l"(gaddr));
}
#define CP_COMMIT() asm volatile("cp.async.commit_group;" ::: "memory")
#define CP_WAIT0()  asm volatile("cp.async.wait_group 0;" ::: "memory")
#define CP_WAIT1()  asm volatile("cp.async.wait_group 1;" ::: "memory")

#define SWZ128(off) ((off) ^ (((off) >> 3) & 0x70))

// ---------------------------------------------------------------------------
// Conversion kernels
// ---------------------------------------------------------------------------
__global__ void split_kernel(const float* __restrict__ in,
                             __nv_bfloat16* __restrict__ hi,
                             __nv_bfloat16* __restrict__ lo)
{
    int i = (blockIdx.x * 256 + threadIdx.x) * 4;
    float4 v = *(const float4*)(in + i);
    __nv_bfloat16 h0 = __float2bfloat16(v.x);
    __nv_bfloat16 h1 = __float2bfloat16(v.y);
    __nv_bfloat16 h2 = __float2bfloat16(v.z);
    __nv_bfloat16 h3 = __float2bfloat16(v.w);
    __nv_bfloat16 l0 = __float2bfloat16(v.x - __bfloat162float(h0));
    __nv_bfloat16 l1 = __float2bfloat16(v.y - __bfloat162float(h1));
    __nv_bfloat16 l2 = __float2bfloat16(v.z - __bfloat162float(h2));
    __nv_bfloat16 l3 = __float2bfloat16(v.w - __bfloat162float(h3));
    ((__nv_bfloat162*)hi)[i / 2]     = __nv_bfloat162(h0, h1);
    ((__nv_bfloat162*)hi)[i / 2 + 1] = __nv_bfloat162(h2, h3);
    ((__nv_bfloat162*)lo)[i / 2]     = __nv_bfloat162(l0, l1);
    ((__nv_bfloat162*)lo)[i / 2 + 1] = __nv_bfloat162(l2, l3);
}

// Batched: transposes+splits all 4 weight matrices in one launch (blockIdx.z)
__global__ void transpose_split4_kernel(
    const float* __restrict__ W0, const float* __restrict__ W1,
    const float* __restrict__ W2, const float* __restrict__ W3,
    __nv_bfloat16* __restrict__ T0h, __nv_bfloat16* __restrict__ T0l,
    __nv_bfloat16* __restrict__ T1h, __nv_bfloat16* __restrict__ T1l,
    __nv_bfloat16* __restrict__ T2h, __nv_bfloat16* __restrict__ T2l,
    __nv_bfloat16* __restrict__ T3h, __nv_bfloat16* __restrict__ T3l)
{
    const float* W;
    __nv_bfloat16 *Th, *Tl;
    switch (blockIdx.z) {
        case 0: W = W0; Th = T0h; Tl = T0l; break;
        case 1: W = W1; Th = T1h; Tl = T1l; break;
        case 2: W = W2; Th = T2h; Tl = T2l; break;
        default: W = W3; Th = T3h; Tl = T3l; break;
    }
    __shared__ float t[32][33];
    const int tx = threadIdx.x, ty = threadIdx.y;
    const int k0 = blockIdx.y * 32;
    const int n0 = blockIdx.x * 32;
    #pragma unroll
    for (int j = 0; j < 4; j++)
        t[ty + j * 8][tx] = W[(size_t)(k0 + ty + j * 8) * MHA_D + n0 + tx];
    __syncthreads();
    #pragma unroll
    for (int j = 0; j < 4; j++) {
        float v = t[tx][ty + j * 8];
        __nv_bfloat16 h = __float2bfloat16(v);
        __nv_bfloat16 l = __float2bfloat16(v - __bfloat162float(h));
        size_t o = (size_t)(n0 + ty + j * 8) * MHA_D + k0 + tx;
        Th[o] = h;
        Tl[o] = l;
    }
}

// ---------------------------------------------------------------------------
// HMMA bf16-split GEMM, cp.async double-buffered, 2 CTAs/SM.
// CTA: 128(M) x 64(N) tile, BK=64. 512 threads, 16 warps 4(m)x4(n),
// warp tile 32x16. Stage = 48 KB, 2 stages = 96 KB -> 2 CTAs per SM.
// QKV=true: fused Q/K/V launch; blockIdx.x>>4 selects weight/output/scale.
// QKV=false: single GEMM (Wo), fp32 output + bias.
// ---------------------------------------------------------------------------
#define GM_M 4096
#define GM_N 1024
#define GM_K 1024
#define GT_M 128
#define GT_N 64
#define GT_K 64
#define GM_NK (GM_K / GT_K)

#define SM_AHI 0
#define SM_ALO 16384
#define SM_BHI 32768
#define SM_BLO 40960
#define STG_B  49152                 // 48 KB per stage
#define SM_GEMM_TOTAL (2 * STG_B)    // 96 KB

template <bool QKV>
__global__ __launch_bounds__(512, 2) void gemm_hmma_kernel(
    const __nv_bfloat16* __restrict__ Ahi, const __nv_bfloat16* __restrict__ Alo,
    const __nv_bfloat16* __restrict__ B0h, const __nv_bfloat16* __restrict__ B0l,
    const __nv_bfloat16* __restrict__ B1h, const __nv_bfloat16* __restrict__ B1l,
    const __nv_bfloat16* __restrict__ B2h, const __nv_bfloat16* __restrict__ B2l,
    const float* __restrict__ bias, float* __restrict__ C,
    __nv_bfloat16* __restrict__ O0h, __nv_bfloat16* __restrict__ O0l,
    __nv_bfloat16* __restrict__ O1h, __nv_bfloat16* __restrict__ O1l,
    __nv_bfloat16* __restrict__ O2h, __nv_bfloat16* __restrict__ O2l)
{
    extern __shared__ char smem[];
    const uint32_t sbase = smem_u32(smem);
    const int tid = threadIdx.x;
    const int wid = tid >> 5;
    const int ln  = tid & 31;
    const int warp_m = wid >> 2;        // 0..3 (32 rows each)
    const int warp_n = wid & 3;         // 0..3 (16 cols each)
    const int m0 = blockIdx.y * GT_M;

    const __nv_bfloat16 *Bh, *Bl;
    __nv_bfloat16 *Ohi, *Olo;
    int n0;
    float scale = 1.0f;
    if (QKV) {
        const int wsel = blockIdx.x >> 4;
        n0 = (blockIdx.x & 15) * GT_N;
        Bh = (wsel == 0) ? B0h : (wsel == 1) ? B1h : B2h;
        Bl = (wsel == 0) ? B0l : (wsel == 1) ? B1l : B2l;
        Ohi = (wsel == 0) ? O0h : (wsel == 1) ? O1h : O2h;
        Olo = (wsel == 0) ? O0l : (wsel == 1) ? O1l : O2l;
        if (wsel == 0) scale = 0.125f;
    } else {
        n0 = blockIdx.x * GT_N;
        Bh = B0h; Bl = B0l;
        Ohi = nullptr; Olo = nullptr;
    }

    float acc[2][2][4];
    #pragma unroll
    for (int i = 0; i < 2; i++)
        #pragma unroll
        for (int j = 0; j < 2; j++)
            #pragma unroll
            for (int q = 0; q < 4; q++) acc[i][j][q] = 0.0f;

    const int lrow = ln & 15;
    const int lhalf = ln >> 4;

    int a_row[2];
    #pragma unroll
    for (int mf = 0; mf < 2; mf++) a_row[mf] = warp_m * 32 + mf * 16 + lrow;
    const int b_row = warp_n * 16 + lrow;

    // Loader geometry:
    //  A tile: 1024 chunk-slots (128 rows x 8 chunks); thread handles slots
    //  {tid, tid+512} for both hi and lo.
    //  B tile: 512 chunk-slots (64 rows x 8 chunks); thread handles slot tid
    //  for hi (tid<512) — all threads: row = tid>>3 covers 0..63. 512 threads
    //  -> one B slot each for hi and lo.
    const int a1_row = tid >> 3, a1_c = tid & 7;
    const int a2_row = 64 + a1_row;
    const uint32_t a1_so = SWZ128((uint32_t)(a1_row * 128 + a1_c * 16));
    const uint32_t a2_so = SWZ128((uint32_t)(a2_row * 128 + a1_c * 16));
    const int b_lrow = tid >> 3, b_c = tid & 7;
    const uint32_t b_so = SWZ128((uint32_t)(b_lrow * 128 + b_c * 16));

    auto issue_stage = [&](int kc, uint32_t stg) {
        const int k0 = kc * GT_K;
        const uint32_t ga1 = (uint32_t)(m0 + a1_row) * GM_K + k0 + a1_c * 8;
        const uint32_t ga2 = (uint32_t)(m0 + a2_row) * GM_K + k0 + a1_c * 8;
        const uint32_t gb  = (uint32_t)(n0 + b_lrow) * GM_K + k0 + b_c * 8;
        cpasync16(sbase + stg + SM_AHI + a1_so, Ahi + ga1);
        cpasync16(sbase + stg + SM_AHI + a2_so, Ahi + ga2);
        cpasync16(sbase + stg + SM_ALO + a1_so, Alo + ga1);
        cpasync16(sbase + stg + SM_ALO + a2_so, Alo + ga2);
        cpasync16(sbase + stg + SM_BHI + b_so, Bh + gb);
        cpasync16(sbase + stg + SM_BLO + b_so, Bl + gb);
        CP_COMMIT();
    };

    issue_stage(0, 0);

    for (int kc = 0; kc < GM_NK; kc++) {
        const uint32_t cur = (uint32_t)(kc & 1) * STG_B;
        if (kc + 1 < GM_NK) {
            issue_stage(kc + 1, (uint32_t)((kc + 1) & 1) * STG_B);
            CP_WAIT1();
        } else {
            CP_WAIT0();
        }
        __syncthreads();

        #pragma unroll
        for (int ks = 0; ks < 4; ks++) {
            const int chunk = ks * 2 + lhalf;
            uint32_t ah[2][4], al[2][4];
            #pragma unroll
            for (int mf = 0; mf < 2; mf++) {
                const int r = a_row[mf];
                const uint32_t off = (uint32_t)(r * 128 + ((chunk ^ (r & 7)) << 4));
                ldmx4(ah[mf], sbase + cur + SM_AHI + off);
                ldmx4(al[mf], sbase + cur + SM_ALO + off);
            }
            uint32_t bh[4], bl[4];
            {
                const uint32_t off = (uint32_t)(b_row * 128 + ((chunk ^ (b_row & 7)) << 4));
                ldmx4(bh, sbase + cur + SM_BHI + off);
                ldmx4(bl, sbase + cur + SM_BLO + off);
            }
            #pragma unroll
            for (int mf = 0; mf < 2; mf++) {
                #pragma unroll
                for (int nf = 0; nf < 2; nf++) {
                    mma16816(acc[mf][nf], ah[mf], bh[nf], bh[2 + nf]);
                    mma16816(acc[mf][nf], ah[mf], bl[nf], bl[2 + nf]);
                    mma16816(acc[mf][nf], al[mf], bh[nf], bh[2 + nf]);
                }
            }
        }
        __syncthreads();
    }

    const int gid = ln >> 2;
    const int tig = ln & 3;
    #pragma unroll
    for (int mf = 0; mf < 2; mf++) {
        #pragma unroll
        for (int nf = 0; nf < 2; nf++) {
            const int col = n0 + warp_n * 16 + nf * 8 + tig * 2;
            const int r0 = m0 + warp_m * 32 + mf * 16 + gid;
            float2 v0, v1;
            v0.x = acc[mf][nf][0]; v0.y = acc[mf][nf][1];
            v1.x = acc[mf][nf][2]; v1.y = acc[mf][nf][3];
            if (QKV) {
                v0.x *= scale; v0.y *= scale; v1.x *= scale; v1.y *= scale;
                __nv_bfloat162 h0 = __float22bfloat162_rn(v0);
                __nv_bfloat162 h1 = __float22bfloat162_rn(v1);
                float2 r0v, r1v;
                r0v.x = v0.x - __bfloat162float(h0.x);
                r0v.y = v0.y - __bfloat162float(h0.y);
                r1v.x = v1.x - __bfloat162float(h1.x);
                r1v.y = v1.y - __bfloat162float(h1.y);
                __nv_bfloat162 l0b = __float22bfloat162_rn(r0v);
                __nv_bfloat162 l1b = __float22bfloat162_rn(r1v);
                *(__nv_bfloat162*)(Ohi + (size_t)r0 * GM_N + col) = h0;
                *(__nv_bfloat162*)(Olo + (size_t)r0 * GM_N + col) = l0b;
                *(__nv_bfloat162*)(Ohi + (size_t)(r0 + 8) * GM_N + col) = h1;
                *(__nv_bfloat162*)(Olo + (size_t)(r0 + 8) * GM_N + col) = l1b;
            } else {
                const float b0v = bias[col], b1v = bias[col + 1];
                v0.x += b0v; v0.y += b1v;
                v1.x += b0v; v1.y += b1v;
                *(float2*)(C + (size_t)r0 * GM_N + col) = v0;
                *(float2*)(C + (size_t)(r0 + 8) * GM_N + col) = v1;
            }
        }
    }
}

// ---------------------------------------------------------------------------
// Tensor-core flash attention (unchanged): causal, bf16-split, 128-query
// tiles, 2-stage pipelined K/V, pair-balanced.
// Grid (8, 32), 256 threads. CTA x handles q-tiles {x, 15-x} -> 34 iters.
// ---------------------------------------------------------------------------
#define SFQ_HI 0
#define SFQ_LO 16384
#define SFS_BASE 32768
#define SFS_SZ 32768
#define SFK_HI 0
#define SFK_LO 8192
#define SFV_HI 16384
#define SFV_LO 24576
#define SF_TOTAL (SFS_BASE + 2 * SFS_SZ)   // 96 KB

__global__ __launch_bounds__(256, 1) void flash_tc_kernel(
    const __nv_bfloat16* __restrict__ Qhi, const __nv_bfloat16* __restrict__ Qlo,
    const __nv_bfloat16* __restrict__ Khi, const __nv_bfloat16* __restrict__ Klo,
    const __nv_bfloat16* __restrict__ Vhi, const __nv_bfloat16* __restrict__ Vlo,
    __nv_bfloat16* __restrict__ Chi, __nv_bfloat16* __restrict__ Clo)
{
    extern __shared__ char smem[];
    const uint32_t sbase = smem_u32(smem);
    const int tid = threadIdx.x;
    const int wid = tid >> 5;
    const int ln  = tid & 31;
    const int b   = blockIdx.y >> 4;
    const int h   = blockIdx.y & 15;
    const size_t base = (size_t)b * MHA_S * MHA_D + (size_t)h * MHA_HD;

    const int lrow  = ln & 15;
    const int lhalf = ln >> 4;
    const int gid   = ln >> 2;
    const int tig   = ln & 3;
    const int arow  = wid * 16 + lrow;   // 0..127

    auto load_q = [&](int q0) {
        #pragma unroll
        for (int cc = 0; cc < 4; cc++) {
            const int id = cc * 256 + tid;         // 0..1023
            const int r = id >> 3;                 // 0..127
            const int c = id & 7;
            const uint32_t so = SWZ128((uint32_t)(r * 128 + c * 16));
            const size_t g = base + (size_t)(q0 + r) * MHA_D + c * 8;
            cpasync16(sbase + SFQ_HI + so, Qhi + g);
            cpasync16(sbase + SFQ_LO + so, Qlo + g);
        }
    };
    auto load_kv = [&](int k0, uint32_t stg) {
        #pragma unroll
        for (int cc = 0; cc < 2; cc++) {
            const int id = cc * 256 + tid;         // 0..511
            const int r = id >> 3;                 // 0..63
            const int c = id & 7;
            const uint32_t so = SWZ128((uint32_t)(r * 128 + c * 16));
            const size_t g = base + (size_t)(k0 + r) * MHA_D + c * 8;
            cpasync16(sbase + stg + SFK_HI + so, Khi + g);
            cpasync16(sbase + stg + SFK_LO + so, Klo + g);
            cpasync16(sbase + stg + SFV_HI + so, Vhi + g);
            cpasync16(sbase + stg + SFV_LO + so, Vlo + g);
        }
        CP_COMMIT();
    };

    #pragma unroll 1
    for (int pass = 0; pass < 2; pass++) {
        const int qt = pass ? (15 - (int)blockIdx.x) : (int)blockIdx.x;
        const int q0 = qt * 128;
        const int ktmax = 2 * qt + 1;

        __syncthreads();   // previous pass fully done before smem reuse

        load_q(q0);
        load_kv(0, SFS_BASE);   // group 1 = Q + kv stage0

        float m0 = -1e30f, m1 = -1e30f, l0 = 0.0f, l1 = 0.0f;
        float o[8][4];
        #pragma unroll
        for (int nf = 0; nf < 8; nf++)
            #pragma unroll
            for (int q = 0; q < 4; q++) o[nf][q] = 0.0f;

        const int row0 = q0 + wid * 16 + gid;
        const int row1 = row0 + 8;

        for (int kt = 0; kt <= ktmax; kt++) {
            const int k0 = kt * 64;
            const uint32_t cur = SFS_BASE + (uint32_t)(kt & 1) * SFS_SZ;
            if (kt < ktmax) {
                load_kv((kt + 1) * 64, SFS_BASE + (uint32_t)((kt + 1) & 1) * SFS_SZ);
                CP_WAIT1();
            } else {
                CP_WAIT0();
            }
            __syncthreads();

            // ---- S = Q K^T ----
            float s[8][4];
            #pragma unroll
            for (int nf = 0; nf < 8; nf++)
                #pragma unroll
                for (int q = 0; q < 4; q++) s[nf][q] = 0.0f;

            #pragma unroll
            for (int ks = 0; ks < 4; ks++) {
                const int chunk = ks * 2 + lhalf;
                const uint32_t offA = (uint32_t)(arow * 128 + ((chunk ^ (arow & 7)) << 4));
                uint32_t ah[4], al[4];
                ldmx4(ah, sbase + SFQ_HI + offA);
                ldmx4(al, sbase + SFQ_LO + offA);
                #pragma unroll
                for (int nfp = 0; nfp < 4; nfp++) {
                    const int brow = nfp * 16 + lrow;
                    const uint32_t offB = (uint32_t)(brow * 128 + ((chunk ^ (brow & 7)) << 4));
                    uint32_t bh[4], bl[4];
                    ldmx4(bh, sbase + cur + SFK_HI + offB);
                    ldmx4(bl, sbase + cur + SFK_LO + offB);
                    #pragma unroll
                    for (int odd = 0; odd < 2; odd++) {
                        const int nf = nfp * 2 + odd;
                        mma16816(s[nf], ah, bh[odd], bh[2 + odd]);
                        mma16816(s[nf], ah, bl[odd], bl[2 + odd]);
                        mma16816(s[nf], al, bh[odd], bh[2 + odd]);
                    }
                }
            }

            // ---- causal mask (only the last two k-tiles can cross diag) ----
            if (kt >= 2 * qt) {
                #pragma unroll
                for (int nf = 0; nf < 8; nf++) {
                    const int c0 = k0 + nf * 8 + tig * 2;
                    if (c0 > row0)     s[nf][0] = -INFINITY;
                    if (c0 + 1 > row0) s[nf][1] = -INFINITY;
                    if (c0 > row1)     s[nf][2] = -INFINITY;
                    if (c0 + 1 > row1) s[nf][3] = -INFINITY;
                }
            }

            // ---- online softmax ----
            float mx0 = m0, mx1 = m1;
            #pragma unroll
            for (int nf = 0; nf < 8; nf++) {
                mx0 = fmaxf(mx0, fmaxf(s[nf][0], s[nf][1]));
                mx1 = fmaxf(mx1, fmaxf(s[nf][2], s[nf][3]));
            }
            mx0 = fmaxf(mx0, __shfl_xor_sync(0xffffffffu, mx0, 1));
            mx0 = fmaxf(mx0, __shfl_xor_sync(0xffffffffu, mx0, 2));
            mx1 = fmaxf(mx1, __shfl_xor_sync(0xffffffffu, mx1, 1));
            mx1 = fmaxf(mx1, __shfl_xor_sync(0xffffffffu, mx1, 2));

            const float corr0 = __expf(m0 - mx0);
            const float corr1 = __expf(m1 - mx1);
            m0 = mx0; m1 = mx1;

            float sum0 = 0.0f, sum1 = 0.0f;
            uint32_t ph[8][2], pl[8][2];
            #pragma unroll
            for (int nf = 0; nf < 8; nf++) {
                float2 p01, p23;
                p01.x = __expf(s[nf][0] - mx0);
                p01.y = __expf(s[nf][1] - mx0);
                p23.x = __expf(s[nf][2] - mx1);
                p23.y = __expf(s[nf][3] - mx1);
                sum0 += p01.x + p01.y;
                sum1 += p23.x + p23.y;
                __nv_bfloat162 h01 = __float22bfloat162_rn(p01);
                __nv_bfloat162 h23 = __float22bfloat162_rn(p23);
                float2 r01, r23;
                r01.x = p01.x - __bfloat162float(h01.x);
                r01.y = p01.y - __bfloat162float(h01.y);
                r23.x = p23.x - __bfloat162float(h23.x);
                r23.y = p23.y - __bfloat162float(h23.y);
                __nv_bfloat162 lo01 = __float22bfloat162_rn(r01);
                __nv_bfloat162 lo23 = __float22bfloat162_rn(r23);
                ph[nf][0] = *(uint32_t*)&h01;
                ph[nf][1] = *(uint32_t*)&h23;
                pl[nf][0] = *(uint32_t*)&lo01;
                pl[nf][1] = *(uint32_t*)&lo23;
            }
            sum0 += __shfl_xor_sync(0xffffffffu, sum0, 1);
            sum0 += __shfl_xor_sync(0xffffffffu, sum0, 2);
            sum1 += __shfl_xor_sync(0xffffffffu, sum1, 1);
            sum1 += __shfl_xor_sync(0xffffffffu, sum1, 2);
            l0 = l0 * corr0 + sum0;
            l1 = l1 * corr1 + sum1;

            #pragma unroll
            for (int nf = 0; nf < 8; nf++) {
                o[nf][0] *= corr0; o[nf][1] *= corr0;
                o[nf][2] *= corr1; o[nf][3] *= corr1;
            }

            // ---- O += P V ----
            #pragma unroll
            for (int kc = 0; kc < 4; kc++) {
                uint32_t aph[4], apl[4];
                aph[0] = ph[2 * kc][0];     aph[1] = ph[2 * kc][1];
                aph[2] = ph[2 * kc + 1][0]; aph[3] = ph[2 * kc + 1][1];
                apl[0] = pl[2 * kc][0];     apl[1] = pl[2 * kc][1];
                apl[2] = pl[2 * kc + 1][0]; apl[3] = pl[2 * kc + 1][1];
                const int g = ln >> 3;
                const int r8 = ln & 7;
                const int key = kc * 16 + (g & 1) * 8 + r8;
                #pragma unroll
                for (int hp = 0; hp < 4; hp++) {
                    const int chunk = hp * 2 + (g >> 1);
                    const uint32_t offV = (uint32_t)(key * 128 + ((chunk ^ (key & 7)) << 4));
                    uint32_t vh[4], vl[4];
                    ldmx4t(vh, sbase + cur + SFV_HI + offV);
                    ldmx4t(vl, sbase + cur + SFV_LO + offV);
                    mma16816(o[2 * hp], aph, vh[0], vh[1]);
                    mma16816(o[2 * hp], aph, vl[0], vl[1]);
                    mma16816(o[2 * hp], apl, vh[0], vh[1]);
                    mma16816(o[2 * hp + 1], aph, vh[2], vh[3]);
                    mma16816(o[2 * hp + 1], aph, vl[2], vl[3]);
                    mma16816(o[2 * hp + 1], apl, vh[2], vh[3]);
                }
            }
            __syncthreads();   // all warps done with `cur` before next prefetch
        }

        // ---- finalize and write ctx as bf16 hi/lo ----
        const float inv0 = 1.0f / l0;
        const float inv1 = 1.0f / l1;
        #pragma unroll
        for (int nf = 0; nf < 8; nf++) {
            const int col = nf * 8 + tig * 2;
            float2 v0, v1;
            v0.x = o[nf][0] * inv0; v0.y = o[nf][1] * inv0;
            v1.x = o[nf][2] * inv1; v1.y = o[nf][3] * inv1;
            __nv_bfloat162 h0 = __float22bfloat162_rn(v0);
            __nv_bfloat162 h1 = __float22bfloat162_rn(v1);
            float2 r0v, r1v;
            r0v.x = v0.x - __bfloat162float(h0.x);
            r0v.y = v0.y - __bfloat162float(h0.y);
            r1v.x = v1.x - __bfloat162float(h1.x);
            r1v.y = v1.y - __bfloat162float(h1.y);
            __nv_bfloat162 l0b = __float22bfloat162_rn(r0v);
            __nv_bfloat162 l1b = __float22bfloat162_rn(r1v);
            const size_t o0 = base + (size_t)row0 * MHA_D + col;
            const size_t o1 = base + (size_t)row1 * MHA_D + col;
            *(__nv_bfloat162*)(Chi + o0) = h0;
            *(__nv_bfloat162*)(Clo + o0) = l0b;
            *(__nv_bfloat162*)(Chi + o1) = h1;
            *(__nv_bfloat162*)(Clo + o1) = l1b;
        }
    }
}

// ---------------------------------------------------------------------------
extern "C" void kernel_launch(void* const* d_in, const int* in_sizes, int n_in,
                              void* d_out, int out_size)
{
    const float* x  = (const float*)d_in[0];
    const float* Wq = (const float*)d_in[1];
    const float* Wk = (const float*)d_in[2];
    const float* Wv = (const float*)d_in[3];
    const float* Wo = (const float*)d_in[4];
    const float* bo = (const float*)d_in[5];
    float* out = (float*)d_out;

    __nv_bfloat16 *xhi, *xlo;
    __nv_bfloat16 *qhi, *qlo, *khi, *klo, *vhi, *vlo, *chi, *clo;
    __nv_bfloat16 *wqh, *wql, *wkh, *wkl, *wvh, *wvl, *woh, *wol;
    cudaGetSymbolAddress((void**)&xhi, g_xhi);
    cudaGetSymbolAddress((void**)&xlo, g_xlo);
    cudaGetSymbolAddress((void**)&qhi, g_qhi);
    cudaGetSymbolAddress((void**)&qlo, g_qlo);
    cudaGetSymbolAddress((void**)&khi, g_khi);
    cudaGetSymbolAddress((void**)&klo, g_klo);
    cudaGetSymbolAddress((void**)&vhi, g_vhi);
    cudaGetSymbolAddress((void**)&vlo, g_vlo);
    cudaGetSymbolAddress((void**)&chi, g_chi);
    cudaGetSymbolAddress((void**)&clo, g_clo);
    cudaGetSymbolAddress((void**)&wqh, g_wqt_hi);
    cudaGetSymbolAddress((void**)&wql, g_wqt_lo);
    cudaGetSymbolAddress((void**)&wkh, g_wkt_hi);
    cudaGetSymbolAddress((void**)&wkl, g_wkt_lo);
    cudaGetSymbolAddress((void**)&wvh, g_wvt_hi);
    cudaGetSymbolAddress((void**)&wvl, g_wvt_lo);
    cudaGetSymbolAddress((void**)&woh, g_wot_hi);
    cudaGetSymbolAddress((void**)&wol, g_wot_lo);

    cudaFuncSetAttribute(flash_tc_kernel,
                         cudaFuncAttributeMaxDynamicSharedMemorySize, SF_TOTAL);
    cudaFuncSetAttribute(gemm_hmma_kernel<true>,
                         cudaFuncAttributeMaxDynamicSharedMemorySize, SM_GEMM_TOTAL);
    cudaFuncSetAttribute(gemm_hmma_kernel<false>,
                         cudaFuncAttributeMaxDynamicSharedMemorySize, SM_GEMM_TOTAL);

    // 1) x -> bf16 hi/lo
    split_kernel<<<NTOK * MHA_D / 1024, 256>>>(x, xhi, xlo);
    // 2) all four weights -> transposed bf16 hi/lo (one launch)
    dim3 tgrid(MHA_D / 32, MHA_D / 32, 4), tblk(32, 8);
    transpose_split4_kernel<<<tgrid, tblk>>>(Wq, Wk, Wv, Wo,
                                             wqh, wql, wkh, wkl,
                                             wvh, wvl, woh, wol);

    // 3) Fused QKV projections -> split bf16 (Q pre-scaled by 1/sqrt(HD))
    dim3 qkv_grid(3 * GM_N / GT_N, GM_M / GT_M);   // (48, 32)
    gemm_hmma_kernel<true><<<qkv_grid, 512, SM_GEMM_TOTAL>>>(
        xhi, xlo,
        wqh, wql, wkh, wkl, wvh, wvl,
        nullptr, nullptr,
        qhi, qlo, khi, klo, vhi, vlo);

    // 4) Pipelined balanced tensor-core causal flash -> split bf16 ctx
    dim3 fa_grid(MHA_S / 256, MHA_B * MHA_H);   // (8, 32)
    flash_tc_kernel<<<fa_grid, 256, SF_TOTAL>>>(qhi, qlo, khi, klo, vhi, vlo, chi, clo);

    // 5) Output projection with bias (fp32 out)
    dim3 wo_grid(GM_N / GT_N, GM_M / GT_M);   // (16, 32)
    gemm_hmma_kernel<false><<<wo_grid, 512, SM_GEMM_TOTAL>>>(
        chi, clo,
        woh, wol, nullptr, nullptr, nullptr, nullptr,
        bo, out,
        nullptr, nullptr, nullptr, nullptr, nullptr, nullptr);
}

// round 15
// speedup vs baseline: 1.2764x; 1.0181x over previous
#include <cuda_runtime.h>
#include <cuda_bf16.h>
#include <math.h>
#include <stdint.h>

#define MHA_B  2
#define MHA_S  2048
#define MHA_D  1024
#define MHA_H  16
#define MHA_HD 64
#define NTOK   (MHA_B * MHA_S)

// ---------------------------------------------------------------------------
// Scratch (__device__ globals; allocation-free rule)
// ---------------------------------------------------------------------------
__device__ __nv_bfloat16 g_xhi[NTOK * MHA_D];
__device__ __nv_bfloat16 g_xlo[NTOK * MHA_D];

__device__ __nv_bfloat16 g_qhi[NTOK * MHA_D];
__device__ __nv_bfloat16 g_qlo[NTOK * MHA_D];
__device__ __nv_bfloat16 g_khi[NTOK * MHA_D];
__device__ __nv_bfloat16 g_klo[NTOK * MHA_D];
__device__ __nv_bfloat16 g_vhi[NTOK * MHA_D];
__device__ __nv_bfloat16 g_vlo[NTOK * MHA_D];
__device__ __nv_bfloat16 g_chi[NTOK * MHA_D];
__device__ __nv_bfloat16 g_clo[NTOK * MHA_D];

__device__ __nv_bfloat16 g_wqt_hi[MHA_D * MHA_D];
__device__ __nv_bfloat16 g_wqt_lo[MHA_D * MHA_D];
__device__ __nv_bfloat16 g_wkt_hi[MHA_D * MHA_D];
__device__ __nv_bfloat16 g_wkt_lo[MHA_D * MHA_D];
__device__ __nv_bfloat16 g_wvt_hi[MHA_D * MHA_D];
__device__ __nv_bfloat16 g_wvt_lo[MHA_D * MHA_D];
__device__ __nv_bfloat16 g_wot_hi[MHA_D * MHA_D];
__device__ __nv_bfloat16 g_wot_lo[MHA_D * MHA_D];

// ---------------------------------------------------------------------------
// Portable (sm_80+) tensor-core + async-copy helpers
// ---------------------------------------------------------------------------
__device__ __forceinline__ uint32_t smem_u32(const void* p) {
    uint32_t a;
    asm("{ .reg .u64 t; cvta.to.shared.u64 t, %1; cvt.u32.u64 %0, t; }"
        : "=r"(a) : "l"(p));
    return a;
}

__device__ __forceinline__ void ldmx4(uint32_t* r, uint32_t addr) {
    asm volatile(
        "ldmatrix.sync.aligned.m8n8.x4.shared.b16 {%0,%1,%2,%3}, [%4];"
        : "=r"(r[0]), "=r"(r[1]), "=r"(r[2]), "=r"(r[3]) : "r"(addr));
}

__device__ __forceinline__ void ldmx4t(uint32_t* r, uint32_t addr) {
    asm volatile(
        "ldmatrix.sync.aligned.m8n8.x4.trans.shared.b16 {%0,%1,%2,%3}, [%4];"
        : "=r"(r[0]), "=r"(r[1]), "=r"(r[2]), "=r"(r[3]) : "r"(addr));
}

__device__ __forceinline__ void mma16816(float* d, const uint32_t* a,
                                         uint32_t b0, uint32_t b1) {
    asm volatile(
        "mma.sync.aligned.m16n8k16.row.col.f32.bf16.bf16.f32 "
        "{%0,%1,%2,%3}, {%4,%5,%6,%7}, {%8,%9}, {%0,%1,%2,%3};"
        : "+f"(d[0]), "+f"(d[1]), "+f"(d[2]), "+f"(d[3])
        : "r"(a[0]), "r"(a[1]), "r"(a[2]), "r"(a[3]), "r"(b0), "r"(b1));
}

__device__ __forceinline__ void cpasync16(uint32_t saddr, const void* gaddr) {
    asm volatile("cp.async.cg.shared.global [%0], [%1], 16;"
                 :: "r"(saddr), "l"(gaddr));
}
#define CP_COMMIT() asm volatile("cp.async.commit_group;" ::: "memory")
#define CP_WAIT0()  asm volatile("cp.async.wait_group 0;" ::: "memory")
#define CP_WAIT1()  asm volatile("cp.async.wait_group 1;" ::: "memory")

#define SWZ128(off) ((off) ^ (((off) >> 3) & 0x70))

// ---------------------------------------------------------------------------
// Conversion kernels
// ---------------------------------------------------------------------------
__global__ void split_kernel(const float* __restrict__ in,
                             __nv_bfloat16* __restrict__ hi,
                             __nv_bfloat16* __restrict__ lo)
{
    int i = (blockIdx.x * 256 + threadIdx.x) * 4;
    float4 v = *(const float4*)(in + i);
    __nv_bfloat16 h0 = __float2bfloat16(v.x);
    __nv_bfloat16 h1 = __float2bfloat16(v.y);
    __nv_bfloat16 h2 = __float2bfloat16(v.z);
    __nv_bfloat16 h3 = __float2bfloat16(v.w);
    __nv_bfloat16 l0 = __float2bfloat16(v.x - __bfloat162float(h0));
    __nv_bfloat16 l1 = __float2bfloat16(v.y - __bfloat162float(h1));
    __nv_bfloat16 l2 = __float2bfloat16(v.z - __bfloat162float(h2));
    __nv_bfloat16 l3 = __float2bfloat16(v.w - __bfloat162float(h3));
    ((__nv_bfloat162*)hi)[i / 2]     = __nv_bfloat162(h0, h1);
    ((__nv_bfloat162*)hi)[i / 2 + 1] = __nv_bfloat162(h2, h3);
    ((__nv_bfloat162*)lo)[i / 2]     = __nv_bfloat162(l0, l1);
    ((__nv_bfloat162*)lo)[i / 2 + 1] = __nv_bfloat162(l2, l3);
}

// Batched: transposes+splits all 4 weight matrices in one launch (blockIdx.z)
__global__ void transpose_split4_kernel(
    const float* __restrict__ W0, const float* __restrict__ W1,
    const float* __restrict__ W2, const float* __restrict__ W3,
    __nv_bfloat16* __restrict__ T0h, __nv_bfloat16* __restrict__ T0l,
    __nv_bfloat16* __restrict__ T1h, __nv_bfloat16* __restrict__ T1l,
    __nv_bfloat16* __restrict__ T2h, __nv_bfloat16* __restrict__ T2l,
    __nv_bfloat16* __restrict__ T3h, __nv_bfloat16* __restrict__ T3l)
{
    const float* W;
    __nv_bfloat16 *Th, *Tl;
    switch (blockIdx.z) {
        case 0: W = W0; Th = T0h; Tl = T0l; break;
        case 1: W = W1; Th = T1h; Tl = T1l; break;
        case 2: W = W2; Th = T2h; Tl = T2l; break;
        default: W = W3; Th = T3h; Tl = T3l; break;
    }
    __shared__ float t[32][33];
    const int tx = threadIdx.x, ty = threadIdx.y;
    const int k0 = blockIdx.y * 32;
    const int n0 = blockIdx.x * 32;
    #pragma unroll
    for (int j = 0; j < 4; j++)
        t[ty + j * 8][tx] = W[(size_t)(k0 + ty + j * 8) * MHA_D + n0 + tx];
    __syncthreads();
    #pragma unroll
    for (int j = 0; j < 4; j++) {
        float v = t[tx][ty + j * 8];
        __nv_bfloat16 h = __float2bfloat16(v);
        __nv_bfloat16 l = __float2bfloat16(v - __bfloat162float(h));
        size_t o = (size_t)(n0 + ty + j * 8) * MHA_D + k0 + tx;
        Th[o] = h;
        Tl[o] = l;
    }
}

// ---------------------------------------------------------------------------
// HMMA bf16-split GEMM, cp.async double-buffered, 2 CTAs/SM (unchanged).
// CTA: 128(M) x 64(N) tile, BK=64. 512 threads, 16 warps 4(m)x4(n).
// ---------------------------------------------------------------------------
#define GM_M 4096
#define GM_N 1024
#define GM_K 1024
#define GT_M 128
#define GT_N 64
#define GT_K 64
#define GM_NK (GM_K / GT_K)

#define SM_AHI 0
#define SM_ALO 16384
#define SM_BHI 32768
#define SM_BLO 40960
#define STG_B  49152
#define SM_GEMM_TOTAL (2 * STG_B)    // 96 KB

template <bool QKV>
__global__ __launch_bounds__(512, 2) void gemm_hmma_kernel(
    const __nv_bfloat16* __restrict__ Ahi, const __nv_bfloat16* __restrict__ Alo,
    const __nv_bfloat16* __restrict__ B0h, const __nv_bfloat16* __restrict__ B0l,
    const __nv_bfloat16* __restrict__ B1h, const __nv_bfloat16* __restrict__ B1l,
    const __nv_bfloat16* __restrict__ B2h, const __nv_bfloat16* __restrict__ B2l,
    const float* __restrict__ bias, float* __restrict__ C,
    __nv_bfloat16* __restrict__ O0h, __nv_bfloat16* __restrict__ O0l,
    __nv_bfloat16* __restrict__ O1h, __nv_bfloat16* __restrict__ O1l,
    __nv_bfloat16* __restrict__ O2h, __nv_bfloat16* __restrict__ O2l)
{
    extern __shared__ char smem[];
    const uint32_t sbase = smem_u32(smem);
    const int tid = threadIdx.x;
    const int wid = tid >> 5;
    const int ln  = tid & 31;
    const int warp_m = wid >> 2;
    const int warp_n = wid & 3;
    const int m0 = blockIdx.y * GT_M;

    const __nv_bfloat16 *Bh, *Bl;
    __nv_bfloat16 *Ohi, *Olo;
    int n0;
    float scale = 1.0f;
    if (QKV) {
        const int wsel = blockIdx.x >> 4;
        n0 = (blockIdx.x & 15) * GT_N;
        Bh = (wsel == 0) ? B0h : (wsel == 1) ? B1h : B2h;
        Bl = (wsel == 0) ? B0l : (wsel == 1) ? B1l : B2l;
        Ohi = (wsel == 0) ? O0h : (wsel == 1) ? O1h : O2h;
        Olo = (wsel == 0) ? O0l : (wsel == 1) ? O1l : O2l;
        if (wsel == 0) scale = 0.125f;
    } else {
        n0 = blockIdx.x * GT_N;
        Bh = B0h; Bl = B0l;
        Ohi = nullptr; Olo = nullptr;
    }

    float acc[2][2][4];
    #pragma unroll
    for (int i = 0; i < 2; i++)
        #pragma unroll
        for (int j = 0; j < 2; j++)
            #pragma unroll
            for (int q = 0; q < 4; q++) acc[i][j][q] = 0.0f;

    const int lrow = ln & 15;
    const int lhalf = ln >> 4;

    int a_row[2];
    #pragma unroll
    for (int mf = 0; mf < 2; mf++) a_row[mf] = warp_m * 32 + mf * 16 + lrow;
    const int b_row = warp_n * 16 + lrow;

    const int a1_row = tid >> 3, a1_c = tid & 7;
    const int a2_row = 64 + a1_row;
    const uint32_t a1_so = SWZ128((uint32_t)(a1_row * 128 + a1_c * 16));
    const uint32_t a2_so = SWZ128((uint32_t)(a2_row * 128 + a1_c * 16));
    const int b_lrow = tid >> 3, b_c = tid & 7;
    const uint32_t b_so = SWZ128((uint32_t)(b_lrow * 128 + b_c * 16));

    auto issue_stage = [&](int kc, uint32_t stg) {
        const int k0 = kc * GT_K;
        const uint32_t ga1 = (uint32_t)(m0 + a1_row) * GM_K + k0 + a1_c * 8;
        const uint32_t ga2 = (uint32_t)(m0 + a2_row) * GM_K + k0 + a1_c * 8;
        const uint32_t gb  = (uint32_t)(n0 + b_lrow) * GM_K + k0 + b_c * 8;
        cpasync16(sbase + stg + SM_AHI + a1_so, Ahi + ga1);
        cpasync16(sbase + stg + SM_AHI + a2_so, Ahi + ga2);
        cpasync16(sbase + stg + SM_ALO + a1_so, Alo + ga1);
        cpasync16(sbase + stg + SM_ALO + a2_so, Alo + ga2);
        cpasync16(sbase + stg + SM_BHI + b_so, Bh + gb);
        cpasync16(sbase + stg + SM_BLO + b_so, Bl + gb);
        CP_COMMIT();
    };

    issue_stage(0, 0);

    for (int kc = 0; kc < GM_NK; kc++) {
        const uint32_t cur = (uint32_t)(kc & 1) * STG_B;
        if (kc + 1 < GM_NK) {
            issue_stage(kc + 1, (uint32_t)((kc + 1) & 1) * STG_B);
            CP_WAIT1();
        } else {
            CP_WAIT0();
        }
        __syncthreads();

        #pragma unroll
        for (int ks = 0; ks < 4; ks++) {
            const int chunk = ks * 2 + lhalf;
            uint32_t ah[2][4], al[2][4];
            #pragma unroll
            for (int mf = 0; mf < 2; mf++) {
                const int r = a_row[mf];
                const uint32_t off = (uint32_t)(r * 128 + ((chunk ^ (r & 7)) << 4));
                ldmx4(ah[mf], sbase + cur + SM_AHI + off);
                ldmx4(al[mf], sbase + cur + SM_ALO + off);
            }
            uint32_t bh[4], bl[4];
            {
                const uint32_t off = (uint32_t)(b_row * 128 + ((chunk ^ (b_row & 7)) << 4));
                ldmx4(bh, sbase + cur + SM_BHI + off);
                ldmx4(bl, sbase + cur + SM_BLO + off);
            }
            #pragma unroll
            for (int mf = 0; mf < 2; mf++) {
                #pragma unroll
                for (int nf = 0; nf < 2; nf++) {
                    mma16816(acc[mf][nf], ah[mf], bh[nf], bh[2 + nf]);
                    mma16816(acc[mf][nf], ah[mf], bl[nf], bl[2 + nf]);
                    mma16816(acc[mf][nf], al[mf], bh[nf], bh[2 + nf]);
                }
            }
        }
        __syncthreads();
    }

    const int gid = ln >> 2;
    const int tig = ln & 3;
    #pragma unroll
    for (int mf = 0; mf < 2; mf++) {
        #pragma unroll
        for (int nf = 0; nf < 2; nf++) {
            const int col = n0 + warp_n * 16 + nf * 8 + tig * 2;
            const int r0 = m0 + warp_m * 32 + mf * 16 + gid;
            float2 v0, v1;
            v0.x = acc[mf][nf][0]; v0.y = acc[mf][nf][1];
            v1.x = acc[mf][nf][2]; v1.y = acc[mf][nf][3];
            if (QKV) {
                v0.x *= scale; v0.y *= scale; v1.x *= scale; v1.y *= scale;
                __nv_bfloat162 h0 = __float22bfloat162_rn(v0);
                __nv_bfloat162 h1 = __float22bfloat162_rn(v1);
                float2 r0v, r1v;
                r0v.x = v0.x - __bfloat162float(h0.x);
                r0v.y = v0.y - __bfloat162float(h0.y);
                r1v.x = v1.x - __bfloat162float(h1.x);
                r1v.y = v1.y - __bfloat162float(h1.y);
                __nv_bfloat162 l0b = __float22bfloat162_rn(r0v);
                __nv_bfloat162 l1b = __float22bfloat162_rn(r1v);
                *(__nv_bfloat162*)(Ohi + (size_t)r0 * GM_N + col) = h0;
                *(__nv_bfloat162*)(Olo + (size_t)r0 * GM_N + col) = l0b;
                *(__nv_bfloat162*)(Ohi + (size_t)(r0 + 8) * GM_N + col) = h1;
                *(__nv_bfloat162*)(Olo + (size_t)(r0 + 8) * GM_N + col) = l1b;
            } else {
                const float b0v = bias[col], b1v = bias[col + 1];
                v0.x += b0v; v0.y += b1v;
                v1.x += b0v; v1.y += b1v;
                *(float2*)(C + (size_t)r0 * GM_N + col) = v0;
                *(float2*)(C + (size_t)(r0 + 8) * GM_N + col) = v1;
            }
        }
    }
}

// ---------------------------------------------------------------------------
// Tensor-core flash attention v4: causal, bf16-split, 128-query tiles,
// 2-stage pipelined K/V, pair-balanced — register-lean (P conversion
// interleaved with PV per 16-key chunk) and forced 2 CTAs/SM.
// Grid (8, 32), 256 threads. CTA x handles q-tiles {x, 15-x} -> 34 iters.
// ---------------------------------------------------------------------------
#define SFQ_HI 0
#define SFQ_LO 16384
#define SFS_BASE 32768
#define SFS_SZ 32768
#define SFK_HI 0
#define SFK_LO 8192
#define SFV_HI 16384
#define SFV_LO 24576
#define SF_TOTAL (SFS_BASE + 2 * SFS_SZ)   // 96 KB

__global__ __launch_bounds__(256, 2) void flash_tc_kernel(
    const __nv_bfloat16* __restrict__ Qhi, const __nv_bfloat16* __restrict__ Qlo,
    const __nv_bfloat16* __restrict__ Khi, const __nv_bfloat16* __restrict__ Klo,
    const __nv_bfloat16* __restrict__ Vhi, const __nv_bfloat16* __restrict__ Vlo,
    __nv_bfloat16* __restrict__ Chi, __nv_bfloat16* __restrict__ Clo)
{
    extern __shared__ char smem[];
    const uint32_t sbase = smem_u32(smem);
    const int tid = threadIdx.x;
    const int wid = tid >> 5;
    const int ln  = tid & 31;
    const int b   = blockIdx.y >> 4;
    const int h   = blockIdx.y & 15;
    const size_t base = (size_t)b * MHA_S * MHA_D + (size_t)h * MHA_HD;

    const int lrow  = ln & 15;
    const int lhalf = ln >> 4;
    const int gid   = ln >> 2;
    const int tig   = ln & 3;
    const int arow  = wid * 16 + lrow;   // 0..127

    auto load_q = [&](int q0) {
        #pragma unroll
        for (int cc = 0; cc < 4; cc++) {
            const int id = cc * 256 + tid;         // 0..1023
            const int r = id >> 3;                 // 0..127
            const int c = id & 7;
            const uint32_t so = SWZ128((uint32_t)(r * 128 + c * 16));
            const size_t g = base + (size_t)(q0 + r) * MHA_D + c * 8;
            cpasync16(sbase + SFQ_HI + so, Qhi + g);
            cpasync16(sbase + SFQ_LO + so, Qlo + g);
        }
    };
    auto load_kv = [&](int k0, uint32_t stg) {
        #pragma unroll
        for (int cc = 0; cc < 2; cc++) {
            const int id = cc * 256 + tid;         // 0..511
            const int r = id >> 3;                 // 0..63
            const int c = id & 7;
            const uint32_t so = SWZ128((uint32_t)(r * 128 + c * 16));
            const size_t g = base + (size_t)(k0 + r) * MHA_D + c * 8;
            cpasync16(sbase + stg + SFK_HI + so, Khi + g);
            cpasync16(sbase + stg + SFK_LO + so, Klo + g);
            cpasync16(sbase + stg + SFV_HI + so, Vhi + g);
            cpasync16(sbase + stg + SFV_LO + so, Vlo + g);
        }
        CP_COMMIT();
    };

    #pragma unroll 1
    for (int pass = 0; pass < 2; pass++) {
        const int qt = pass ? (15 - (int)blockIdx.x) : (int)blockIdx.x;
        const int q0 = qt * 128;
        const int ktmax = 2 * qt + 1;

        __syncthreads();   // previous pass fully done before smem reuse

        load_q(q0);
        load_kv(0, SFS_BASE);   // group 1 = Q + kv stage0

        float m0 = -1e30f, m1 = -1e30f, l0 = 0.0f, l1 = 0.0f;
        float o[8][4];
        #pragma unroll
        for (int nf = 0; nf < 8; nf++)
            #pragma unroll
            for (int q = 0; q < 4; q++) o[nf][q] = 0.0f;

        const int row0 = q0 + wid * 16 + gid;
        const int row1 = row0 + 8;

        for (int kt = 0; kt <= ktmax; kt++) {
            const int k0 = kt * 64;
            const uint32_t cur = SFS_BASE + (uint32_t)(kt & 1) * SFS_SZ;
            if (kt < ktmax) {
                load_kv((kt + 1) * 64, SFS_BASE + (uint32_t)((kt + 1) & 1) * SFS_SZ);
                CP_WAIT1();
            } else {
                CP_WAIT0();
            }
            __syncthreads();

            // ---- S = Q K^T ----
            float s[8][4];
            #pragma unroll
            for (int nf = 0; nf < 8; nf++)
                #pragma unroll
                for (int q = 0; q < 4; q++) s[nf][q] = 0.0f;

            #pragma unroll
            for (int ks = 0; ks < 4; ks++) {
                const int chunk = ks * 2 + lhalf;
                const uint32_t offA = (uint32_t)(arow * 128 + ((chunk ^ (arow & 7)) << 4));
                uint32_t ah[4], al[4];
                ldmx4(ah, sbase + SFQ_HI + offA);
                ldmx4(al, sbase + SFQ_LO + offA);
                #pragma unroll
                for (int nfp = 0; nfp < 4; nfp++) {
                    const int brow = nfp * 16 + lrow;
                    const uint32_t offB = (uint32_t)(brow * 128 + ((chunk ^ (brow & 7)) << 4));
                    uint32_t bh[4], bl[4];
                    ldmx4(bh, sbase + cur + SFK_HI + offB);
                    ldmx4(bl, sbase + cur + SFK_LO + offB);
                    #pragma unroll
                    for (int odd = 0; odd < 2; odd++) {
                        const int nf = nfp * 2 + odd;
                        mma16816(s[nf], ah, bh[odd], bh[2 + odd]);
                        mma16816(s[nf], ah, bl[odd], bl[2 + odd]);
                        mma16816(s[nf], al, bh[odd], bh[2 + odd]);
                    }
                }
            }

            // ---- causal mask (only the last two k-tiles can cross diag) ----
            if (kt >= 2 * qt) {
                #pragma unroll
                for (int nf = 0; nf < 8; nf++) {
                    const int c0 = k0 + nf * 8 + tig * 2;
                    if (c0 > row0)     s[nf][0] = -INFINITY;
                    if (c0 + 1 > row0) s[nf][1] = -INFINITY;
                    if (c0 > row1)     s[nf][2] = -INFINITY;
                    if (c0 + 1 > row1) s[nf][3] = -INFINITY;
                }
            }

            // ---- online softmax: row max + correction ----
            float mx0 = m0, mx1 = m1;
            #pragma unroll
            for (int nf = 0; nf < 8; nf++) {
                mx0 = fmaxf(mx0, fmaxf(s[nf][0], s[nf][1]));
                mx1 = fmaxf(mx1, fmaxf(s[nf][2], s[nf][3]));
            }
            mx0 = fmaxf(mx0, __shfl_xor_sync(0xffffffffu, mx0, 1));
            mx0 = fmaxf(mx0, __shfl_xor_sync(0xffffffffu, mx0, 2));
            mx1 = fmaxf(mx1, __shfl_xor_sync(0xffffffffu, mx1, 1));
            mx1 = fmaxf(mx1, __shfl_xor_sync(0xffffffffu, mx1, 2));

            const float corr0 = __expf(m0 - mx0);
            const float corr1 = __expf(m1 - mx1);
            m0 = mx0; m1 = mx1;

            #pragma unroll
            for (int nf = 0; nf < 8; nf++) {
                o[nf][0] *= corr0; o[nf][1] *= corr0;
                o[nf][2] *= corr1; o[nf][3] *= corr1;
            }

            // ---- exp + bf16-split conversion interleaved with PV per chunk
            //      (keeps P fragments live only 8 regs at a time) ----
            float sum0 = 0.0f, sum1 = 0.0f;
            const int g = ln >> 3;
            const int r8 = ln & 7;
            #pragma unroll
            for (int kc = 0; kc < 4; kc++) {
                uint32_t aph[4], apl[4];
                #pragma unroll
                for (int j = 0; j < 2; j++) {
                    const int nf = 2 * kc + j;
                    float2 p01, p23;
                    p01.x = __expf(s[nf][0] - mx0);
                    p01.y = __expf(s[nf][1] - mx0);
                    p23.x = __expf(s[nf][2] - mx1);
                    p23.y = __expf(s[nf][3] - mx1);
                    sum0 += p01.x + p01.y;
                    sum1 += p23.x + p23.y;
                    __nv_bfloat162 h01 = __float22bfloat162_rn(p01);
                    __nv_bfloat162 h23 = __float22bfloat162_rn(p23);
                    float2 r01, r23;
                    r01.x = p01.x - __bfloat162float(h01.x);
                    r01.y = p01.y - __bfloat162float(h01.y);
                    r23.x = p23.x - __bfloat162float(h23.x);
                    r23.y = p23.y - __bfloat162float(h23.y);
                    __nv_bfloat162 lo01 = __float22bfloat162_rn(r01);
                    __nv_bfloat162 lo23 = __float22bfloat162_rn(r23);
                    aph[2 * j]     = *(uint32_t*)&h01;
                    aph[2 * j + 1] = *(uint32_t*)&h23;
                    apl[2 * j]     = *(uint32_t*)&lo01;
                    apl[2 * j + 1] = *(uint32_t*)&lo23;
                }
                const int key = kc * 16 + (g & 1) * 8 + r8;
                #pragma unroll
                for (int hp = 0; hp < 4; hp++) {
                    const int chunk = hp * 2 + (g >> 1);
                    const uint32_t offV = (uint32_t)(key * 128 + ((chunk ^ (key & 7)) << 4));
                    uint32_t vh[4], vl[4];
                    ldmx4t(vh, sbase + cur + SFV_HI + offV);
                    ldmx4t(vl, sbase + cur + SFV_LO + offV);
                    mma16816(o[2 * hp], aph, vh[0], vh[1]);
                    mma16816(o[2 * hp], aph, vl[0], vl[1]);
                    mma16816(o[2 * hp], apl, vh[0], vh[1]);
                    mma16816(o[2 * hp + 1], aph, vh[2], vh[3]);
                    mma16816(o[2 * hp + 1], aph, vl[2], vl[3]);
                    mma16816(o[2 * hp + 1], apl, vh[2], vh[3]);
                }
            }

            sum0 += __shfl_xor_sync(0xffffffffu, sum0, 1);
            sum0 += __shfl_xor_sync(0xffffffffu, sum0, 2);
            sum1 += __shfl_xor_sync(0xffffffffu, sum1, 1);
            sum1 += __shfl_xor_sync(0xffffffffu, sum1, 2);
            l0 = l0 * corr0 + sum0;
            l1 = l1 * corr1 + sum1;

            __syncthreads();   // all warps done with `cur` before next prefetch
        }

        // ---- finalize and write ctx as bf16 hi/lo ----
        const float inv0 = 1.0f / l0;
        const float inv1 = 1.0f / l1;
        #pragma unroll
        for (int nf = 0; nf < 8; nf++) {
            const int col = nf * 8 + tig * 2;
            float2 v0, v1;
            v0.x = o[nf][0] * inv0; v0.y = o[nf][1] * inv0;
            v1.x = o[nf][2] * inv1; v1.y = o[nf][3] * inv1;
            __nv_bfloat162 h0 = __float22bfloat162_rn(v0);
            __nv_bfloat162 h1 = __float22bfloat162_rn(v1);
            float2 r0v, r1v;
            r0v.x = v0.x - __bfloat162float(h0.x);
            r0v.y = v0.y - __bfloat162float(h0.y);
            r1v.x = v1.x - __bfloat162float(h1.x);
            r1v.y = v1.y - __bfloat162float(h1.y);
            __nv_bfloat162 l0b = __float22bfloat162_rn(r0v);
            __nv_bfloat162 l1b = __float22bfloat162_rn(r1v);
            const size_t o0 = base + (size_t)row0 * MHA_D + col;
            const size_t o1 = base + (size_t)row1 * MHA_D + col;
            *(__nv_bfloat162*)(Chi + o0) = h0;
            *(__nv_bfloat162*)(Clo + o0) = l0b;
            *(__nv_bfloat162*)(Chi + o1) = h1;
            *(__nv_bfloat162*)(Clo + o1) = l1b;
        }
    }
}

// ---------------------------------------------------------------------------
extern "C" void kernel_launch(void* const* d_in, const int* in_sizes, int n_in,
                              void* d_out, int out_size)
{
    const float* x  = (const float*)d_in[0];
    const float* Wq = (const float*)d_in[1];
    const float* Wk = (const float*)d_in[2];
    const float* Wv = (const float*)d_in[3];
    const float* Wo = (const float*)d_in[4];
    const float* bo = (const float*)d_in[5];
    float* out = (float*)d_out;

    __nv_bfloat16 *xhi, *xlo;
    __nv_bfloat16 *qhi, *qlo, *khi, *klo, *vhi, *vlo, *chi, *clo;
    __nv_bfloat16 *wqh, *wql, *wkh, *wkl, *wvh, *wvl, *woh, *wol;
    cudaGetSymbolAddress((void**)&xhi, g_xhi);
    cudaGetSymbolAddress((void**)&xlo, g_xlo);
    cudaGetSymbolAddress((void**)&qhi, g_qhi);
    cudaGetSymbolAddress((void**)&qlo, g_qlo);
    cudaGetSymbolAddress((void**)&khi, g_khi);
    cudaGetSymbolAddress((void**)&klo, g_klo);
    cudaGetSymbolAddress((void**)&vhi, g_vhi);
    cudaGetSymbolAddress((void**)&vlo, g_vlo);
    cudaGetSymbolAddress((void**)&chi, g_chi);
    cudaGetSymbolAddress((void**)&clo, g_clo);
    cudaGetSymbolAddress((void**)&wqh, g_wqt_hi);
    cudaGetSymbolAddress((void**)&wql, g_wqt_lo);
    cudaGetSymbolAddress((void**)&wkh, g_wkt_hi);
    cudaGetSymbolAddress((void**)&wkl, g_wkt_lo);
    cudaGetSymbolAddress((void**)&wvh, g_wvt_hi);
    cudaGetSymbolAddress((void**)&wvl, g_wvt_lo);
    cudaGetSymbolAddress((void**)&woh, g_wot_hi);
    cudaGetSymbolAddress((void**)&wol, g_wot_lo);

    cudaFuncSetAttribute(flash_tc_kernel,
                         cudaFuncAttributeMaxDynamicSharedMemorySize, SF_TOTAL);
    cudaFuncSetAttribute(gemm_hmma_kernel<true>,
                         cudaFuncAttributeMaxDynamicSharedMemorySize, SM_GEMM_TOTAL);
    cudaFuncSetAttribute(gemm_hmma_kernel<false>,
                         cudaFuncAttributeMaxDynamicSharedMemorySize, SM_GEMM_TOTAL);

    // 1) x -> bf16 hi/lo
    split_kernel<<<NTOK * MHA_D / 1024, 256>>>(x, xhi, xlo);
    // 2) all four weights -> transposed bf16 hi/lo (one launch)
    dim3 tgrid(MHA_D / 32, MHA_D / 32, 4), tblk(32, 8);
    transpose_split4_kernel<<<tgrid, tblk>>>(Wq, Wk, Wv, Wo,
                                             wqh, wql, wkh, wkl,
                                             wvh, wvl, woh, wol);

    // 3) Fused QKV projections -> split bf16 (Q pre-scaled by 1/sqrt(HD))
    dim3 qkv_grid(3 * GM_N / GT_N, GM_M / GT_M);   // (48, 32)
    gemm_hmma_kernel<true><<<qkv_grid, 512, SM_GEMM_TOTAL>>>(
        xhi, xlo,
        wqh, wql, wkh, wkl, wvh, wvl,
        nullptr, nullptr,
        qhi, qlo, khi, klo, vhi, vlo);

    // 4) Pipelined balanced tensor-core causal flash -> split bf16 ctx
    dim3 fa_grid(MHA_S / 256, MHA_B * MHA_H);   // (8, 32)
    flash_tc_kernel<<<fa_grid, 256, SF_TOTAL>>>(qhi, qlo, khi, klo, vhi, vlo, chi, clo);

    // 5) Output projection with bias (fp32 out)
    dim3 wo_grid(GM_N / GT_N, GM_M / GT_M);   // (16, 32)
    gemm_hmma_kernel<false><<<wo_grid, 512, SM_GEMM_TOTAL>>>(
        chi, clo,
        woh, wol, nullptr, nullptr, nullptr, nullptr,
        bo, out,
        nullptr, nullptr, nullptr, nullptr, nullptr, nullptr);
}